// round 2
// baseline (speedup 1.0000x reference)
#include <cuda_runtime.h>
#include <math.h>

#define BB    32
#define SS    256
#define HH    1024
#define NROWS 8192
#define NBLK  128   // persistent RNN CTAs: jg(8 x 128 cols) * kg(16 x 64 k)

__device__ int    g_sorted[BB];
__device__ int    g_rev[BB];
__device__ int    g_tok[NROWS];
__device__ float  g_hidden[2 * BB * HH];
__device__ float  g_pre[NROWS * HH];
__device__ float  g_h1[(size_t)NROWS * HH];
__device__ float  g_h2[(size_t)NROWS * HH];
__device__ float  g_part[16][BB * HH];
__device__ float  g_pw[64 * HH];          // packed: head_w rows 0..32, tp2 rows 36..51
__device__ float  g_logits[NROWS * 64];
__device__ float  g_hl[NROWS];
__device__ float  g_ct[NROWS];
__device__ float  g_nll[NROWS];
__device__ float  g_zero[64];
__device__ unsigned          g_cnt;
__device__ volatile unsigned g_flag;

// ---------- prep ----------
__global__ void k_prep(const int* __restrict__ len) {
    if (threadIdx.x == 0) {
        int idx[BB];
        for (int i = 0; i < BB; i++) idx[i] = i;
        for (int i = 1; i < BB; i++) {               // stable desc insertion sort
            int v = idx[i], lv = len[v], j = i - 1;
            while (j >= 0 && len[idx[j]] < lv) { idx[j + 1] = idx[j]; j--; }
            idx[j + 1] = v;
        }
        for (int p = 0; p < BB; p++) { g_sorted[p] = idx[p]; g_rev[idx[p]] = p; }
    }
}

__global__ void k_tok(const int* __restrict__ inp) {
    int r = blockIdx.x * blockDim.x + threadIdx.x;
    if (r < NROWS) g_tok[r] = inp[g_sorted[r >> 8] * SS + (r & 255)];
}

// hid = z @ l2h_w^T + b   (flat view == .view(2,B,H))
__global__ void k_hidden(const float* __restrict__ z, const float* __restrict__ w,
                         const float* __restrict__ b) {
    int o = blockIdx.x * blockDim.x + threadIdx.x;
    if (o >= 2 * BB * HH) return;
    const float* zr = z + (o >> 11) * 256;
    const float* wr = w + (size_t)(o & 2047) * 256;
    float acc = 0.f;
#pragma unroll 8
    for (int k = 0; k < 256; k++) acc = fmaf(zr[k], wr[k], acc);
    g_hidden[o] = acc + b[o & 2047];
}

__global__ void k_pack(const float* __restrict__ head_w, const float* __restrict__ tp2) {
    int i = blockIdx.x * blockDim.x + threadIdx.x;
    if (i >= 64 * HH) return;
    int row = i >> 10, c = i & 1023;
    float v = 0.f;
    if (row < 33)                 v = head_w[row * HH + c];
    else if (row >= 36 && row < 52) v = tp2[(row - 36) * HH + c];
    g_pw[i] = v;
}

// ---------- SGEMM: C[n][m] = A[row(n)][:K] . Bw[m][:K] + b1[m]+b2[m] ----------
// BM=128 BN=64 BK=16, 256 thr, 8x4 reg tile. gather!=0 => A row = g_tok[n]
__global__ void __launch_bounds__(256)
k_sgemm(const float* __restrict__ A, const float* __restrict__ Bw,
        const float* __restrict__ b1, const float* __restrict__ b2,
        float* __restrict__ C, int K, int M, int gather) {
    __shared__ __align__(16) float As[16][128];
    __shared__ __align__(16) float Bs[16][64];
    int tid = threadIdx.x, tx = tid & 15, ty = tid >> 4;
    int n0 = blockIdx.x * 128, m0 = blockIdx.y * 64;
    float acc[8][4];
#pragma unroll
    for (int r = 0; r < 8; r++)
#pragma unroll
        for (int c = 0; c < 4; c++) acc[r][c] = 0.f;

    for (int k0 = 0; k0 < K; k0 += 16) {
#pragma unroll
        for (int i = 0; i < 2; i++) {
            int id = tid * 2 + i, r = id >> 2, kq = (id & 3) * 4;
            int grow = n0 + r;
            int arow = gather ? g_tok[grow] : grow;
            float4 v = *(const float4*)(A + (size_t)arow * K + k0 + kq);
            As[kq][r] = v.x; As[kq + 1][r] = v.y; As[kq + 2][r] = v.z; As[kq + 3][r] = v.w;
        }
        {
            int m = tid >> 2, kq = (tid & 3) * 4;
            float4 v = *(const float4*)(Bw + (size_t)(m0 + m) * K + k0 + kq);
            Bs[kq][m] = v.x; Bs[kq + 1][m] = v.y; Bs[kq + 2][m] = v.z; Bs[kq + 3][m] = v.w;
        }
        __syncthreads();
#pragma unroll
        for (int k = 0; k < 16; k++) {
            float4 a0 = *(float4*)&As[k][ty * 8];
            float4 a1 = *(float4*)&As[k][ty * 8 + 4];
            float4 bv = *(float4*)&Bs[k][tx * 4];
            float a[8] = {a0.x, a0.y, a0.z, a0.w, a1.x, a1.y, a1.z, a1.w};
            float b[4] = {bv.x, bv.y, bv.z, bv.w};
#pragma unroll
            for (int r = 0; r < 8; r++)
#pragma unroll
                for (int c = 0; c < 4; c++) acc[r][c] = fmaf(a[r], b[c], acc[r][c]);
        }
        __syncthreads();
    }
    float bias[4];
#pragma unroll
    for (int c = 0; c < 4; c++) { int m = m0 + tx * 4 + c; bias[c] = b1[m] + b2[m]; }
#pragma unroll
    for (int r = 0; r < 8; r++) {
        int n = n0 + ty * 8 + r;
        float4 v = make_float4(acc[r][0] + bias[0], acc[r][1] + bias[1],
                               acc[r][2] + bias[2], acc[r][3] + bias[3]);
        *(float4*)(C + (size_t)n * M + m0 + tx * 4) = v;
    }
}

// ---------- persistent RNN layer ----------
__device__ __forceinline__ void gridbar(unsigned& sense) {
    __threadfence();
    __syncthreads();
    if (threadIdx.x == 0) {
        if (atomicAdd(&g_cnt, 1u) == NBLK - 1) {
            atomicExch(&g_cnt, 0u);
            __threadfence();
            g_flag = sense ^ 1u;
        } else {
            while (g_flag == sense) __nanosleep(64);
        }
    }
    __syncthreads();
    sense ^= 1u;
    __threadfence();
}

__global__ void __launch_bounds__(128, 1)
k_rnn(const float* __restrict__ Whh, const float* __restrict__ pre,
      const float* __restrict__ h0, float* __restrict__ hseq) {
    __shared__ float Ws[64 * 132];   // [k][j] 64x128 (+pad)
    __shared__ float HS[64 * 36];    // [k][b] 64x32 (+pad)
    int tid = threadIdx.x, bid = blockIdx.x;
    int jg = bid >> 4, kg = bid & 15;
    int j0 = jg * 128, k0 = kg * 64;

    for (int i = tid; i < 64 * 128; i += 128) {   // coalesced over k
        int k = i & 63, j = i >> 6;
        Ws[k * 132 + j] = Whh[(size_t)(j0 + j) * HH + k0 + k];
    }
    unsigned sense = g_flag;
    __syncthreads();

    int tb = (tid & 7) * 4;       // 4 batch rows
    int tj = (tid >> 3) * 8;      // 8 j cols
    float* part = &g_part[kg][0];

    for (int t = 0; t < SS; t++) {
        for (int i = tid; i < 32 * 64; i += 128) {    // k fastest -> coalesced gmem
            int b = i >> 6, k = i & 63;
            float v = (t == 0) ? h0[b * HH + k0 + k]
                               : __ldcg(&hseq[((size_t)b * SS + (t - 1)) * HH + k0 + k]);
            HS[k * 36 + b] = v;
        }
        __syncthreads();

        float acc[4][8];
#pragma unroll
        for (int i = 0; i < 4; i++)
#pragma unroll
            for (int j = 0; j < 8; j++) acc[i][j] = 0.f;

#pragma unroll 8
        for (int k = 0; k < 64; k++) {
            float4 hv = *(float4*)&HS[k * 36 + tb];
            float4 w0 = *(float4*)&Ws[k * 132 + tj];
            float4 w1 = *(float4*)&Ws[k * 132 + tj + 4];
            float a[4] = {hv.x, hv.y, hv.z, hv.w};
            float w[8] = {w0.x, w0.y, w0.z, w0.w, w1.x, w1.y, w1.z, w1.w};
#pragma unroll
            for (int i = 0; i < 4; i++)
#pragma unroll
                for (int j = 0; j < 8; j++) acc[i][j] = fmaf(a[i], w[j], acc[i][j]);
        }
#pragma unroll
        for (int i = 0; i < 4; i++) {
            __stcg((float4*)&part[(tb + i) * HH + j0 + tj],
                   make_float4(acc[i][0], acc[i][1], acc[i][2], acc[i][3]));
            __stcg((float4*)&part[(tb + i) * HH + j0 + tj + 4],
                   make_float4(acc[i][4], acc[i][5], acc[i][6], acc[i][7]));
        }
        gridbar(sense);

        for (int o = bid * 128 + tid; o < BB * HH; o += NBLK * 128) {
            int b = o >> 10, j = o & 1023;
            float s = pre[((size_t)b * SS + t) * HH + j];
#pragma unroll
            for (int q = 0; q < 16; q++) s += __ldcg(&g_part[q][o]);
            __stcg(&hseq[((size_t)b * SS + t) * HH + j], tanhf(s));
        }
        gridbar(sense);
    }
}

// ---------- head logsumexp (33 logits) ----------
__global__ void k_head() {
    int r = blockIdx.x * blockDim.x + threadIdx.x;
    if (r >= NROWS) return;
    int rr = g_rev[r >> 8] * 256 + (r & 255);
    const float* L = g_logits + (size_t)rr * 64;
    float m = -1e30f;
    for (int j = 0; j < 33; j++) m = fmaxf(m, L[j]);
    float se = 0.f;
    for (int j = 0; j < 33; j++) se += __expf(L[j] - m);
    g_hl[r] = m + logf(se);
}

// ---------- tail cluster 2 (19000 words x 16): warp=word-stripe, lane=row ----------
__global__ void __launch_bounds__(128)
k_tail2(const float* __restrict__ tw2, const int* __restrict__ target) {
    __shared__ float s_tl[32], s_m[4][32], s_s[4][32];
    int tid = threadIdx.x, warp = tid >> 5, lane = tid & 31;
    int r = blockIdx.x * 32 + lane;
    int tgt = target[r];
    int rr = g_rev[r >> 8] * 256 + (r & 255);
    const float4* pr = (const float4*)&g_logits[(size_t)rr * 64 + 36];
    float4 P0 = pr[0], P1 = pr[1], P2 = pr[2], P3 = pr[3];
    int wt = tgt - 1000;
    float m = -1e30f, se = 0.f;
    for (int w = warp; w < 19000; w += 4) {
        const float4* wr = (const float4*)(tw2 + (size_t)w * 16);
        float4 A = wr[0], B = wr[1], C = wr[2], D = wr[3];
        float l = P0.x * A.x; l = fmaf(P0.y, A.y, l); l = fmaf(P0.z, A.z, l); l = fmaf(P0.w, A.w, l);
        l = fmaf(P1.x, B.x, l); l = fmaf(P1.y, B.y, l); l = fmaf(P1.z, B.z, l); l = fmaf(P1.w, B.w, l);
        l = fmaf(P2.x, C.x, l); l = fmaf(P2.y, C.y, l); l = fmaf(P2.z, C.z, l); l = fmaf(P2.w, C.w, l);
        l = fmaf(P3.x, D.x, l); l = fmaf(P3.y, D.y, l); l = fmaf(P3.z, D.z, l); l = fmaf(P3.w, D.w, l);
        if (w == wt) s_tl[lane] = l;
        if (l > m) { se = se * __expf(m - l) + 1.f; m = l; }
        else       se += __expf(l - m);
    }
    s_m[warp][lane] = m; s_s[warp][lane] = se;
    __syncthreads();
    if (warp == 0) {
        float M = s_m[0][lane];
        for (int q = 1; q < 4; q++) M = fmaxf(M, s_m[q][lane]);
        float S = 0.f;
        for (int q = 0; q < 4; q++) S += s_s[q][lane] * __expf(s_m[q][lane] - M);
        if (tgt >= 1000) g_ct[r] = (M + logf(S)) - s_tl[lane];
    }
}

// ---------- tail clusters 0/1 (rare rows), early exit ----------
__global__ void __launch_bounds__(128)
k_tail01(const float* __restrict__ tp0, const float* __restrict__ tw0,
         const float* __restrict__ tp1, const float* __restrict__ tw1,
         const int* __restrict__ target) {
    int r = blockIdx.x;
    int tgt = target[r];
    if (tgt < 30 || tgt >= 1000) return;
    int lo, nw, d; const float *P, *W;
    if (tgt < 100) { lo = 30; nw = 70; d = 256; P = tp0; W = tw0; }
    else           { lo = 100; nw = 900; d = 64; P = tp1; W = tw1; }
    int tid = threadIdx.x, lane = tid & 31, warp = tid >> 5;
    int rr = g_rev[r >> 8] * 256 + (r & 255);
    __shared__ float xs[HH], proj[256], rm[128], rs[128], s_tl;
    const float* xr = g_h2 + (size_t)rr * HH;
    for (int i = tid; i < HH; i += 128) xs[i] = xr[i];
    __syncthreads();
    for (int p = warp; p < d; p += 4) {
        const float* wr = P + (size_t)p * HH;
        float s = 0.f;
        for (int k = lane; k < HH; k += 32) s = fmaf(xs[k], wr[k], s);
#pragma unroll
        for (int off = 16; off; off >>= 1) s += __shfl_xor_sync(0xffffffffu, s, off);
        if (lane == 0) proj[p] = s;
    }
    __syncthreads();
    float m = -1e30f, se = 0.f;
    for (int w = tid; w < nw; w += 128) {
        const float* wr = W + (size_t)w * d;
        float l = 0.f;
        for (int k = 0; k < d; k++) l = fmaf(proj[k], wr[k], l);
        if (w == tgt - lo) s_tl = l;
        if (l > m) { se = se * __expf(m - l) + 1.f; m = l; }
        else       se += __expf(l - m);
    }
    rm[tid] = m; rs[tid] = se;
    __syncthreads();
    if (tid == 0) {
        float M = -1e30f;
        for (int i = 0; i < 128; i++) M = fmaxf(M, rm[i]);
        float S = 0.f;
        for (int i = 0; i < 128; i++) S += rs[i] * __expf(rm[i] - M);
        g_ct[r] = (M + logf(S)) - s_tl;
    }
}

// ---------- assemble + deterministic sum ----------
__global__ void k_final(const int* __restrict__ target) {
    int r = blockIdx.x * blockDim.x + threadIdx.x;
    if (r >= NROWS) return;
    int tgt = target[r];
    int rr = g_rev[r >> 8] * 256 + (r & 255);
    float nll;
    if (tgt == 0) nll = 0.f;
    else if (tgt < 30) nll = g_hl[r] - g_logits[(size_t)rr * 64 + tgt];
    else {
        int ci = tgt < 100 ? 0 : (tgt < 1000 ? 1 : 2);
        nll = (g_hl[r] - g_logits[(size_t)rr * 64 + 30 + ci]) + g_ct[r];
    }
    g_nll[r] = nll;
}

__global__ void k_sum(float* __restrict__ out) {
    __shared__ float sd[256];
    int tid = threadIdx.x;
    float s = 0.f;
    for (int i = tid; i < NROWS; i += 256) s += g_nll[i];
    sd[tid] = s;
    __syncthreads();
    for (int st = 128; st; st >>= 1) {
        if (tid < st) sd[tid] += sd[tid + st];
        __syncthreads();
    }
    if (tid == 0) out[0] = sd[0];
}

extern "C" void kernel_launch(void* const* d_in, const int* in_sizes, int n_in,
                              void* d_out, int out_size) {
    const float* z      = (const float*)d_in[0];
    const float* emb    = (const float*)d_in[1];
    const float* l2h_w  = (const float*)d_in[2];
    const float* l2h_b  = (const float*)d_in[3];
    const float* r0wih  = (const float*)d_in[4];
    const float* r0whh  = (const float*)d_in[5];
    const float* r0bih  = (const float*)d_in[6];
    const float* r0bhh  = (const float*)d_in[7];
    const float* r1wih  = (const float*)d_in[8];
    const float* r1whh  = (const float*)d_in[9];
    const float* r1bih  = (const float*)d_in[10];
    const float* r1bhh  = (const float*)d_in[11];
    const float* head_w = (const float*)d_in[12];
    const float* tp0    = (const float*)d_in[13];
    const float* tw0    = (const float*)d_in[14];
    const float* tp1    = (const float*)d_in[15];
    const float* tw1    = (const float*)d_in[16];
    const float* tp2    = (const float*)d_in[17];
    const float* tw2    = (const float*)d_in[18];
    const int*   inp    = (const int*)d_in[19];
    const int*   target = (const int*)d_in[20];
    const int*   length = (const int*)d_in[21];
    float* out = (float*)d_out;

    float* gh1 = nullptr; float* gh2 = nullptr; float* gz = nullptr; float* gpw = nullptr;
    float* ghid = nullptr; float* gpre = nullptr; float* glog = nullptr;
    cudaGetSymbolAddress((void**)&gh1, g_h1);
    cudaGetSymbolAddress((void**)&gh2, g_h2);
    cudaGetSymbolAddress((void**)&gz, g_zero);
    cudaGetSymbolAddress((void**)&gpw, g_pw);
    cudaGetSymbolAddress((void**)&ghid, g_hidden);
    cudaGetSymbolAddress((void**)&gpre, g_pre);
    cudaGetSymbolAddress((void**)&glog, g_logits);

    k_prep<<<1, 32>>>(length);
    k_tok<<<NROWS / 256, 256>>>(inp);
    k_hidden<<<(2 * BB * HH) / 256, 256>>>(z, l2h_w, l2h_b);
    k_pack<<<64 * HH / 256, 256>>>(head_w, tp2);

    // layer 0 input pre-activations: emb[tok] @ W0ih^T + b
    k_sgemm<<<dim3(64, 16), 256>>>(emb, r0wih, r0bih, r0bhh, gpre, 512, HH, 1);
    k_rnn<<<NBLK, 128>>>(r0whh, gpre, ghid, gh1);
    // layer 1
    k_sgemm<<<dim3(64, 16), 256>>>(gh1, r1wih, r1bih, r1bhh, gpre, HH, HH, 0);
    k_rnn<<<NBLK, 128>>>(r1whh, gpre, ghid + BB * HH, gh2);

    // packed head + tail2-proj logits: [8192 x 64]
    k_sgemm<<<dim3(64, 1), 256>>>(gh2, gpw, gz, gz, glog, HH, 64, 0);

    k_head<<<NROWS / 256, 256>>>();
    k_tail2<<<NROWS / 32, 128>>>(tw2, target);
    k_tail01<<<NROWS, 128>>>(tp0, tw0, tp1, tw1, target);
    k_final<<<NROWS / 256, 256>>>(target);
    k_sum<<<1, 256>>>(out);
    (void)in_sizes; (void)n_in; (void)out_size;
}

// round 4
// speedup vs baseline: 1.2850x; 1.2850x over previous
#include <cuda_runtime.h>
#include <math.h>

#define BB    32
#define SS    256
#define HH    1024
#define NROWS 8192
#define NBLK  128   // persistent RNN CTAs: jg(8 x 128 cols) * kg(16 x 64 k)

typedef unsigned long long ull;

__device__ int    g_sorted[BB];
__device__ int    g_rev[BB];
__device__ int    g_tok[NROWS];
__device__ float  g_hidden[2 * BB * HH];
__device__ float  g_pre[NROWS * HH];
__device__ float  g_h1[(size_t)NROWS * HH];
__device__ float  g_h2[(size_t)NROWS * HH];
__device__ float  g_part[16][BB * HH];
__device__ float  g_pw[64 * HH];          // packed: head_w rows 0..32, tp2 rows 36..51
__device__ float  g_logits[NROWS * 64];
__device__ float  g_hl[NROWS];
__device__ float  g_ct[NROWS];
__device__ float  g_nll[NROWS];
__device__ float  g_zero[64];
__device__ unsigned          g_cnt;
__device__ volatile unsigned g_flag;

// packed fp32x2 FMA: d = a*b + d  (per-lane IEEE fp32)
__device__ __forceinline__ void ffma2(ull& d, ull a, ull b) {
    asm("fma.rn.f32x2 %0, %1, %2, %0;" : "+l"(d) : "l"(a), "l"(b));
}
__device__ __forceinline__ ull packdup(float x) {
    ull r;
    asm("mov.b64 %0, {%1, %1};" : "=l"(r) : "r"(__float_as_uint(x)));
    return r;
}
__device__ __forceinline__ float pairsum(ull v) {
    float2 f = *reinterpret_cast<float2*>(&v);
    return f.x + f.y;
}

// ---------- prep ----------
__global__ void k_prep(const int* __restrict__ len) {
    if (threadIdx.x == 0) {
        g_cnt = 0; g_flag = 0;
        int idx[BB];
        for (int i = 0; i < BB; i++) idx[i] = i;
        for (int i = 1; i < BB; i++) {               // stable desc insertion sort
            int v = idx[i], lv = len[v], j = i - 1;
            while (j >= 0 && len[idx[j]] < lv) { idx[j + 1] = idx[j]; j--; }
            idx[j + 1] = v;
        }
        for (int p = 0; p < BB; p++) { g_sorted[p] = idx[p]; g_rev[idx[p]] = p; }
    }
}

__global__ void k_tok(const int* __restrict__ inp) {
    int r = blockIdx.x * blockDim.x + threadIdx.x;
    if (r < NROWS) g_tok[r] = inp[g_sorted[r >> 8] * SS + (r & 255)];
}

// hid = z @ l2h_w^T + b   (flat view == .view(2,B,H))
__global__ void k_hidden(const float* __restrict__ z, const float* __restrict__ w,
                         const float* __restrict__ b) {
    int o = blockIdx.x * blockDim.x + threadIdx.x;
    if (o >= 2 * BB * HH) return;
    const float* zr = z + (o >> 11) * 256;
    const float* wr = w + (size_t)(o & 2047) * 256;
    float acc = 0.f;
#pragma unroll 8
    for (int k = 0; k < 256; k++) acc = fmaf(zr[k], wr[k], acc);
    g_hidden[o] = acc + b[o & 2047];
}

__global__ void k_pack(const float* __restrict__ head_w, const float* __restrict__ tp2) {
    int i = blockIdx.x * blockDim.x + threadIdx.x;
    if (i >= 64 * HH) return;
    int row = i >> 10, c = i & 1023;
    float v = 0.f;
    if (row < 33)                 v = head_w[row * HH + c];
    else if (row >= 36 && row < 52) v = tp2[(row - 36) * HH + c];
    g_pw[i] = v;
}

// ---------- SGEMM (f32x2): C[n][m] = A[row(n)][:K] . Bw[m][:K] + b1[m]+b2[m] ----------
// BM=128 BN=64 BK=16, 256 thr, 8x4 reg tile (col-paired). gather!=0 => A row = g_tok[n]
__global__ void __launch_bounds__(256)
k_sgemm(const float* __restrict__ A, const float* __restrict__ Bw,
        const float* __restrict__ b1, const float* __restrict__ b2,
        float* __restrict__ C, int K, int M, int gather) {
    __shared__ __align__(16) float As[16][128];
    __shared__ __align__(16) float Bs[16][64];
    int tid = threadIdx.x, tx = tid & 15, ty = tid >> 4;
    int n0 = blockIdx.x * 128, m0 = blockIdx.y * 64;
    ull acc2[8][2];
#pragma unroll
    for (int r = 0; r < 8; r++) { acc2[r][0] = 0ull; acc2[r][1] = 0ull; }

    for (int k0 = 0; k0 < K; k0 += 16) {
#pragma unroll
        for (int i = 0; i < 2; i++) {
            int id = tid * 2 + i, r = id >> 2, kq = (id & 3) * 4;
            int grow = n0 + r;
            int arow = gather ? g_tok[grow] : grow;
            float4 v = *(const float4*)(A + (size_t)arow * K + k0 + kq);
            As[kq][r] = v.x; As[kq + 1][r] = v.y; As[kq + 2][r] = v.z; As[kq + 3][r] = v.w;
        }
        {
            int m = tid >> 2, kq = (tid & 3) * 4;
            float4 v = *(const float4*)(Bw + (size_t)(m0 + m) * K + k0 + kq);
            Bs[kq][m] = v.x; Bs[kq + 1][m] = v.y; Bs[kq + 2][m] = v.z; Bs[kq + 3][m] = v.w;
        }
        __syncthreads();
#pragma unroll
        for (int k = 0; k < 16; k++) {
            float4 a0 = *(float4*)&As[k][ty * 8];
            float4 a1 = *(float4*)&As[k][ty * 8 + 4];
            const ull* bp = (const ull*)&Bs[k][tx * 4];
            ull b01 = bp[0], b23 = bp[1];
            float a[8] = {a0.x, a0.y, a0.z, a0.w, a1.x, a1.y, a1.z, a1.w};
#pragma unroll
            for (int r = 0; r < 8; r++) {
                ull ap = packdup(a[r]);
                ffma2(acc2[r][0], ap, b01);
                ffma2(acc2[r][1], ap, b23);
            }
        }
        __syncthreads();
    }
    float bias[4];
#pragma unroll
    for (int c = 0; c < 4; c++) { int m = m0 + tx * 4 + c; bias[c] = b1[m] + b2[m]; }
#pragma unroll
    for (int r = 0; r < 8; r++) {
        int n = n0 + ty * 8 + r;
        float2 p0 = *(float2*)&acc2[r][0];
        float2 p1 = *(float2*)&acc2[r][1];
        float4 v = make_float4(p0.x + bias[0], p0.y + bias[1],
                               p1.x + bias[2], p1.y + bias[3]);
        *(float4*)(C + (size_t)n * M + m0 + tx * 4) = v;
    }
}

// ---------- monotonic-epoch grid barrier ----------
__device__ __forceinline__ void gridbar_ep(unsigned ep) {
    __syncthreads();
    if (threadIdx.x == 0) {
        __threadfence();
        unsigned old = atomicAdd(&g_cnt, 1u);
        if (old == ep * NBLK - 1) {
            g_flag = ep;
            __threadfence();
        } else {
            while (g_flag < ep) __nanosleep(64);
            __threadfence();
        }
    }
    __syncthreads();
}

// ---------- persistent RNN layer (f32x2, k-packed dot) ----------
// 128 CTAs = 8 jg (128 cols) x 16 kg (64 k). 128 threads, tile 4b x 8j.
__global__ void __launch_bounds__(128, 1)
k_rnn(const float* __restrict__ Whh, const float* __restrict__ pre,
      const float* __restrict__ h0, float* __restrict__ hseq, unsigned ep0) {
    __shared__ __align__(16) float Ws[128 * 68];   // [j][k], k-major, pad 68
    __shared__ __align__(16) float HS[32 * 68];    // [b][k], k-major, pad 68
    int tid = threadIdx.x, bid = blockIdx.x;
    int jg = bid >> 4, kg = bid & 15;
    int j0 = jg * 128, k0 = kg * 64;

    for (int i = tid; i < 128 * 64; i += 128) {   // coalesced gmem, conflict-free smem
        int k = i & 63, j = i >> 6;
        Ws[j * 68 + k] = Whh[(size_t)(j0 + j) * HH + k0 + k];
    }
    __syncthreads();

    int tb = (tid & 7) * 4;       // 4 batch rows
    int tj = (tid >> 3) * 8;      // 8 j cols
    float* part = &g_part[kg][0];

    for (int t = 0; t < SS; t++) {
        for (int i = tid; i < 32 * 64; i += 128) {
            int k = i & 63, b = i >> 6;
            float v = (t == 0) ? h0[b * HH + k0 + k]
                               : __ldcg(&hseq[((size_t)b * SS + (t - 1)) * HH + k0 + k]);
            HS[b * 68 + k] = v;
        }
        __syncthreads();

        ull acc[4][8];
#pragma unroll
        for (int i = 0; i < 4; i++)
#pragma unroll
            for (int j = 0; j < 8; j++) acc[i][j] = 0ull;

        const float* hr0 = &HS[(tb + 0) * 68];
        const float* hr1 = &HS[(tb + 1) * 68];
        const float* hr2 = &HS[(tb + 2) * 68];
        const float* hr3 = &HS[(tb + 3) * 68];

#pragma unroll 2
        for (int k = 0; k < 64; k += 4) {
            ulonglong2 h[4];
            h[0] = *(const ulonglong2*)&hr0[k];
            h[1] = *(const ulonglong2*)&hr1[k];
            h[2] = *(const ulonglong2*)&hr2[k];
            h[3] = *(const ulonglong2*)&hr3[k];
#pragma unroll
            for (int jh = 0; jh < 8; jh += 4) {
                ulonglong2 w[4];
#pragma unroll
                for (int j = 0; j < 4; j++)
                    w[j] = *(const ulonglong2*)&Ws[(tj + jh + j) * 68 + k];
#pragma unroll
                for (int i = 0; i < 4; i++)
#pragma unroll
                    for (int j = 0; j < 4; j++) {
                        ffma2(acc[i][jh + j], h[i].x, w[j].x);
                        ffma2(acc[i][jh + j], h[i].y, w[j].y);
                    }
            }
        }
#pragma unroll
        for (int i = 0; i < 4; i++) {
            float4 v0 = make_float4(pairsum(acc[i][0]), pairsum(acc[i][1]),
                                    pairsum(acc[i][2]), pairsum(acc[i][3]));
            float4 v1 = make_float4(pairsum(acc[i][4]), pairsum(acc[i][5]),
                                    pairsum(acc[i][6]), pairsum(acc[i][7]));
            __stcg((float4*)&part[(tb + i) * HH + j0 + tj], v0);
            __stcg((float4*)&part[(tb + i) * HH + j0 + tj + 4], v1);
        }
        gridbar_ep(ep0 + 2 * t + 1);

        for (int o = bid * 128 + tid; o < BB * HH; o += NBLK * 128) {
            int b = o >> 10, j = o & 1023;
            float s = pre[((size_t)b * SS + t) * HH + j];
#pragma unroll
            for (int q = 0; q < 16; q++) s += __ldcg(&g_part[q][o]);
            __stcg(&hseq[((size_t)b * SS + t) * HH + j], tanhf(s));
        }
        gridbar_ep(ep0 + 2 * t + 2);
    }
}

// ---------- head logsumexp (33 logits) ----------
__global__ void k_head() {
    int r = blockIdx.x * blockDim.x + threadIdx.x;
    if (r >= NROWS) return;
    int rr = g_rev[r >> 8] * 256 + (r & 255);
    const float* L = g_logits + (size_t)rr * 64;
    float m = -1e30f;
    for (int j = 0; j < 33; j++) m = fmaxf(m, L[j]);
    float se = 0.f;
    for (int j = 0; j < 33; j++) se += __expf(L[j] - m);
    g_hl[r] = m + logf(se);
}

// ---------- tail cluster 2 (19000 words x 16): warp=word-stripe, lane=row ----------
__global__ void __launch_bounds__(128)
k_tail2(const float* __restrict__ tw2, const int* __restrict__ target) {
    __shared__ float s_tl[32], s_m[4][32], s_s[4][32];
    int tid = threadIdx.x, warp = tid >> 5, lane = tid & 31;
    int r = blockIdx.x * 32 + lane;
    int tgt = target[r];
    int rr = g_rev[r >> 8] * 256 + (r & 255);
    const float4* pr = (const float4*)&g_logits[(size_t)rr * 64 + 36];
    float4 P0 = pr[0], P1 = pr[1], P2 = pr[2], P3 = pr[3];
    int wt = tgt - 1000;
    float m = -1e30f, se = 0.f;
    for (int w = warp; w < 19000; w += 4) {
        const float4* wr = (const float4*)(tw2 + (size_t)w * 16);
        float4 A = wr[0], B = wr[1], C = wr[2], D = wr[3];
        float l = P0.x * A.x; l = fmaf(P0.y, A.y, l); l = fmaf(P0.z, A.z, l); l = fmaf(P0.w, A.w, l);
        l = fmaf(P1.x, B.x, l); l = fmaf(P1.y, B.y, l); l = fmaf(P1.z, B.z, l); l = fmaf(P1.w, B.w, l);
        l = fmaf(P2.x, C.x, l); l = fmaf(P2.y, C.y, l); l = fmaf(P2.z, C.z, l); l = fmaf(P2.w, C.w, l);
        l = fmaf(P3.x, D.x, l); l = fmaf(P3.y, D.y, l); l = fmaf(P3.z, D.z, l); l = fmaf(P3.w, D.w, l);
        if (w == wt) s_tl[lane] = l;
        if (l > m) { se = se * __expf(m - l) + 1.f; m = l; }
        else       se += __expf(l - m);
    }
    s_m[warp][lane] = m; s_s[warp][lane] = se;
    __syncthreads();
    if (warp == 0) {
        float M = s_m[0][lane];
        for (int q = 1; q < 4; q++) M = fmaxf(M, s_m[q][lane]);
        float S = 0.f;
        for (int q = 0; q < 4; q++) S += s_s[q][lane] * __expf(s_m[q][lane] - M);
        if (tgt >= 1000) g_ct[r] = (M + logf(S)) - s_tl[lane];
    }
}

// ---------- tail clusters 0/1 (rare rows), early exit ----------
__global__ void __launch_bounds__(128)
k_tail01(const float* __restrict__ tp0, const float* __restrict__ tw0,
         const float* __restrict__ tp1, const float* __restrict__ tw1,
         const int* __restrict__ target) {
    int r = blockIdx.x;
    int tgt = target[r];
    if (tgt < 30 || tgt >= 1000) return;
    int lo, nw, d; const float *P, *W;
    if (tgt < 100) { lo = 30; nw = 70; d = 256; P = tp0; W = tw0; }
    else           { lo = 100; nw = 900; d = 64; P = tp1; W = tw1; }
    int tid = threadIdx.x, lane = tid & 31, warp = tid >> 5;
    int rr = g_rev[r >> 8] * 256 + (r & 255);
    __shared__ float xs[HH], proj[256], rm[128], rs[128], s_tl;
    const float* xr = g_h2 + (size_t)rr * HH;
    for (int i = tid; i < HH; i += 128) xs[i] = xr[i];
    __syncthreads();
    for (int p = warp; p < d; p += 4) {
        const float* wr = P + (size_t)p * HH;
        float s = 0.f;
        for (int k = lane; k < HH; k += 32) s = fmaf(xs[k], wr[k], s);
#pragma unroll
        for (int off = 16; off; off >>= 1) s += __shfl_xor_sync(0xffffffffu, s, off);
        if (lane == 0) proj[p] = s;
    }
    __syncthreads();
    float m = -1e30f, se = 0.f;
    for (int w = tid; w < nw; w += 128) {
        const float* wr = W + (size_t)w * d;
        float l = 0.f;
        for (int k = 0; k < d; k++) l = fmaf(proj[k], wr[k], l);
        if (w == tgt - lo) s_tl = l;
        if (l > m) { se = se * __expf(m - l) + 1.f; m = l; }
        else       se += __expf(l - m);
    }
    rm[tid] = m; rs[tid] = se;
    __syncthreads();
    if (tid == 0) {
        float M = -1e30f;
        for (int i = 0; i < 128; i++) M = fmaxf(M, rm[i]);
        float S = 0.f;
        for (int i = 0; i < 128; i++) S += rs[i] * __expf(rm[i] - M);
        g_ct[r] = (M + logf(S)) - s_tl;
    }
}

// ---------- assemble + deterministic sum ----------
__global__ void k_final(const int* __restrict__ target) {
    int r = blockIdx.x * blockDim.x + threadIdx.x;
    if (r >= NROWS) return;
    int tgt = target[r];
    int rr = g_rev[r >> 8] * 256 + (r & 255);
    float nll;
    if (tgt == 0) nll = 0.f;
    else if (tgt < 30) nll = g_hl[r] - g_logits[(size_t)rr * 64 + tgt];
    else {
        int ci = tgt < 100 ? 0 : (tgt < 1000 ? 1 : 2);
        nll = (g_hl[r] - g_logits[(size_t)rr * 64 + 30 + ci]) + g_ct[r];
    }
    g_nll[r] = nll;
}

__global__ void k_sum(float* __restrict__ out) {
    __shared__ float sd[256];
    int tid = threadIdx.x;
    float s = 0.f;
    for (int i = tid; i < NROWS; i += 256) s += g_nll[i];
    sd[tid] = s;
    __syncthreads();
    for (int st = 128; st; st >>= 1) {
        if (tid < st) sd[tid] += sd[tid + st];
        __syncthreads();
    }
    if (tid == 0) out[0] = sd[0];
}

extern "C" void kernel_launch(void* const* d_in, const int* in_sizes, int n_in,
                              void* d_out, int out_size) {
    const float* z      = (const float*)d_in[0];
    const float* emb    = (const float*)d_in[1];
    const float* l2h_w  = (const float*)d_in[2];
    const float* l2h_b  = (const float*)d_in[3];
    const float* r0wih  = (const float*)d_in[4];
    const float* r0whh  = (const float*)d_in[5];
    const float* r0bih  = (const float*)d_in[6];
    const float* r0bhh  = (const float*)d_in[7];
    const float* r1wih  = (const float*)d_in[8];
    const float* r1whh  = (const float*)d_in[9];
    const float* r1bih  = (const float*)d_in[10];
    const float* r1bhh  = (const float*)d_in[11];
    const float* head_w = (const float*)d_in[12];
    const float* tp0    = (const float*)d_in[13];
    const float* tw0    = (const float*)d_in[14];
    const float* tp1    = (const float*)d_in[15];
    const float* tw1    = (const float*)d_in[16];
    const float* tp2    = (const float*)d_in[17];
    const float* tw2    = (const float*)d_in[18];
    const int*   inp    = (const int*)d_in[19];
    const int*   target = (const int*)d_in[20];
    const int*   length = (const int*)d_in[21];
    float* out = (float*)d_out;

    float* gh1 = nullptr; float* gh2 = nullptr; float* gz = nullptr; float* gpw = nullptr;
    float* ghid = nullptr; float* gpre = nullptr; float* glog = nullptr;
    cudaGetSymbolAddress((void**)&gh1, g_h1);
    cudaGetSymbolAddress((void**)&gh2, g_h2);
    cudaGetSymbolAddress((void**)&gz, g_zero);
    cudaGetSymbolAddress((void**)&gpw, g_pw);
    cudaGetSymbolAddress((void**)&ghid, g_hidden);
    cudaGetSymbolAddress((void**)&gpre, g_pre);
    cudaGetSymbolAddress((void**)&glog, g_logits);

    k_prep<<<1, 32>>>(length);
    k_tok<<<NROWS / 256, 256>>>(inp);
    k_hidden<<<(2 * BB * HH) / 256, 256>>>(z, l2h_w, l2h_b);
    k_pack<<<64 * HH / 256, 256>>>(head_w, tp2);

    // layer 0 input pre-activations: emb[tok] @ W0ih^T + b
    k_sgemm<<<dim3(64, 16), 256>>>(emb, r0wih, r0bih, r0bhh, gpre, 512, HH, 1);
    k_rnn<<<NBLK, 128>>>(r0whh, gpre, ghid, gh1, 0u);
    // layer 1
    k_sgemm<<<dim3(64, 16), 256>>>(gh1, r1wih, r1bih, r1bhh, gpre, HH, HH, 0);
    k_rnn<<<NBLK, 128>>>(r1whh, gpre, ghid + BB * HH, gh2, 2u * SS);

    // packed head + tail2-proj logits: [8192 x 64]
    k_sgemm<<<dim3(64, 1), 256>>>(gh2, gpw, gz, gz, glog, HH, 64, 0);

    k_head<<<NROWS / 256, 256>>>();
    k_tail2<<<NROWS / 32, 128>>>(tw2, target);
    k_tail01<<<NROWS, 128>>>(tp0, tw0, tp1, tw1, target);
    k_final<<<NROWS / 256, 256>>>(target);
    k_sum<<<1, 256>>>(out);
    (void)in_sizes; (void)n_in; (void)out_size;
}

// round 6
// speedup vs baseline: 1.3475x; 1.0486x over previous
#include <cuda_runtime.h>
#include <math.h>

#define BB    32
#define SS    256
#define HH    1024
#define NROWS 8192
#define NBLK  128   // persistent RNN CTAs: each owns 8 j-columns, full k

typedef unsigned long long ull;

__device__ int    g_sorted[BB];
__device__ int    g_rev[BB];
__device__ int    g_tok[NROWS];
__device__ float  g_hidden[2 * BB * HH];
__device__ float  g_pre[NROWS * HH];
__device__ float  g_h1[(size_t)NROWS * HH];
__device__ float  g_h2[(size_t)NROWS * HH];
__device__ float  g_pw[64 * HH];          // packed: head_w rows 0..32, tp2 rows 36..51
__device__ float  g_logits[NROWS * 64];
__device__ float  g_hl[NROWS];
__device__ float  g_ct[NROWS];
__device__ float  g_nll[NROWS];
__device__ float  g_zero[64];
__device__ unsigned          g_cnt;
__device__ volatile unsigned g_flag;

// packed fp32x2 FMA: d = a*b + d  (per-lane IEEE fp32)
__device__ __forceinline__ void ffma2(ull& d, ull a, ull b) {
    asm("fma.rn.f32x2 %0, %1, %2, %0;" : "+l"(d) : "l"(a), "l"(b));
}
__device__ __forceinline__ ull packdup(float x) {
    ull r;
    asm("mov.b64 %0, {%1, %1};" : "=l"(r) : "r"(__float_as_uint(x)));
    return r;
}
__device__ __forceinline__ float pairsum(ull v) {
    float2 f = *reinterpret_cast<float2*>(&v);
    return f.x + f.y;
}

// ---------- prep ----------
__global__ void k_prep(const int* __restrict__ len) {
    if (threadIdx.x == 0) {
        g_cnt = 0; g_flag = 0;
        int idx[BB];
        for (int i = 0; i < BB; i++) idx[i] = i;
        for (int i = 1; i < BB; i++) {               // stable desc insertion sort
            int v = idx[i], lv = len[v], j = i - 1;
            while (j >= 0 && len[idx[j]] < lv) { idx[j + 1] = idx[j]; j--; }
            idx[j + 1] = v;
        }
        for (int p = 0; p < BB; p++) { g_sorted[p] = idx[p]; g_rev[idx[p]] = p; }
    }
}

__global__ void k_tok(const int* __restrict__ inp) {
    int r = blockIdx.x * blockDim.x + threadIdx.x;
    if (r < NROWS) g_tok[r] = inp[g_sorted[r >> 8] * SS + (r & 255)];
}

// hid = z @ l2h_w^T + b   (flat view == .view(2,B,H))
__global__ void k_hidden(const float* __restrict__ z, const float* __restrict__ w,
                         const float* __restrict__ b) {
    int o = blockIdx.x * blockDim.x + threadIdx.x;
    if (o >= 2 * BB * HH) return;
    const float* zr = z + (o >> 11) * 256;
    const float* wr = w + (size_t)(o & 2047) * 256;
    float acc = 0.f;
#pragma unroll 8
    for (int k = 0; k < 256; k++) acc = fmaf(zr[k], wr[k], acc);
    g_hidden[o] = acc + b[o & 2047];
}

__global__ void k_pack(const float* __restrict__ head_w, const float* __restrict__ tp2) {
    int i = blockIdx.x * blockDim.x + threadIdx.x;
    if (i >= 64 * HH) return;
    int row = i >> 10, c = i & 1023;
    float v = 0.f;
    if (row < 33)                 v = head_w[row * HH + c];
    else if (row >= 36 && row < 52) v = tp2[(row - 36) * HH + c];
    g_pw[i] = v;
}

// ---------- SGEMM (f32x2): C[n][m] = A[row(n)][:K] . Bw[m][:K] + b1[m]+b2[m] ----------
// BM=128 BN=64 BK=16, 256 thr, 8x4 reg tile (col-paired). gather!=0 => A row = g_tok[n]
__global__ void __launch_bounds__(256)
k_sgemm(const float* __restrict__ A, const float* __restrict__ Bw,
        const float* __restrict__ b1, const float* __restrict__ b2,
        float* __restrict__ C, int K, int M, int gather) {
    __shared__ __align__(16) float As[16][128];
    __shared__ __align__(16) float Bs[16][64];
    int tid = threadIdx.x, tx = tid & 15, ty = tid >> 4;
    int n0 = blockIdx.x * 128, m0 = blockIdx.y * 64;
    ull acc2[8][2];
#pragma unroll
    for (int r = 0; r < 8; r++) { acc2[r][0] = 0ull; acc2[r][1] = 0ull; }

    for (int k0 = 0; k0 < K; k0 += 16) {
#pragma unroll
        for (int i = 0; i < 2; i++) {
            int id = tid * 2 + i, r = id >> 2, kq = (id & 3) * 4;
            int grow = n0 + r;
            int arow = gather ? g_tok[grow] : grow;
            float4 v = *(const float4*)(A + (size_t)arow * K + k0 + kq);
            As[kq][r] = v.x; As[kq + 1][r] = v.y; As[kq + 2][r] = v.z; As[kq + 3][r] = v.w;
        }
        {
            int m = tid >> 2, kq = (tid & 3) * 4;
            float4 v = *(const float4*)(Bw + (size_t)(m0 + m) * K + k0 + kq);
            Bs[kq][m] = v.x; Bs[kq + 1][m] = v.y; Bs[kq + 2][m] = v.z; Bs[kq + 3][m] = v.w;
        }
        __syncthreads();
#pragma unroll
        for (int k = 0; k < 16; k++) {
            float4 a0 = *(float4*)&As[k][ty * 8];
            float4 a1 = *(float4*)&As[k][ty * 8 + 4];
            const ull* bp = (const ull*)&Bs[k][tx * 4];
            ull b01 = bp[0], b23 = bp[1];
            float a[8] = {a0.x, a0.y, a0.z, a0.w, a1.x, a1.y, a1.z, a1.w};
#pragma unroll
            for (int r = 0; r < 8; r++) {
                ull ap = packdup(a[r]);
                ffma2(acc2[r][0], ap, b01);
                ffma2(acc2[r][1], ap, b23);
            }
        }
        __syncthreads();
    }
    float bias[4];
#pragma unroll
    for (int c = 0; c < 4; c++) { int m = m0 + tx * 4 + c; bias[c] = b1[m] + b2[m]; }
#pragma unroll
    for (int r = 0; r < 8; r++) {
        int n = n0 + ty * 8 + r;
        float2 p0 = *(float2*)&acc2[r][0];
        float2 p1 = *(float2*)&acc2[r][1];
        float4 v = make_float4(p0.x + bias[0], p0.y + bias[1],
                               p1.x + bias[2], p1.y + bias[3]);
        *(float4*)(C + (size_t)n * M + m0 + tx * 4) = v;
    }
}

// ---------- monotonic-epoch grid barrier ----------
__device__ __forceinline__ void gridbar_ep(unsigned ep) {
    __syncthreads();
    if (threadIdx.x == 0) {
        __threadfence();
        unsigned old = atomicAdd(&g_cnt, 1u);
        if (old == ep * NBLK - 1) {
            g_flag = ep;
            __threadfence();
        } else {
            while (g_flag < ep) __nanosleep(64);
            __threadfence();
        }
    }
    __syncthreads();
}

// ---------- persistent RNN layer: 128 CTAs x 256 thr ----------
// CTA owns 8 j-columns, full k. Warp w (0..7) handles k in [128w,128w+128), lane = b.
// h(t-1) streamed from L2 into registers (pipelined), W broadcast from smem.
// Intra-CTA smem reduce of 8 warp-partials, tanh, store. ONE grid barrier/step.
__global__ void __launch_bounds__(256, 1)
k_rnn(const float* __restrict__ Whh, const float* __restrict__ pre,
      const float* __restrict__ h0, float* __restrict__ hseq, unsigned ep0) {
    __shared__ __align__(16) float Ws[8 * HH];      // [jj][k]
    __shared__ float Part[8 * 32 * 9];              // [w][b][jj] stride 9
    int tid = threadIdx.x, bid = blockIdx.x;
    int w = tid >> 5, lane = tid & 31;
    int j0 = bid * 8;

    {   // load W slice: 8 rows x 1024, coalesced float4
        const float4* src = (const float4*)(Whh + (size_t)j0 * HH);
        float4* dst = (float4*)Ws;
        for (int i = tid; i < 8 * 256; i += 256) dst[i] = src[i];
    }
    __syncthreads();

    int k0 = w * 128;
    // reduce-phase mapping: thread -> (b2, jj2)
    int b2 = tid >> 3, jj2 = tid & 7;
    const float* pre_base = pre + ((size_t)b2 * SS) * HH + j0 + jj2;
    float* out_base = hseq + ((size_t)b2 * SS) * HH + j0 + jj2;

    for (int t = 0; t < SS; t++) {
        const float* hb = (t == 0)
            ? (h0 + lane * HH + k0)
            : (hseq + ((size_t)lane * SS + (t - 1)) * HH + k0);

        ull acc[8];
#pragma unroll
        for (int j = 0; j < 8; j++) acc[j] = 0ull;

        // prefetch 8 quads (32 floats) into registers
        double2 hbuf[8];
#pragma unroll
        for (int p = 0; p < 8; p++)
            hbuf[p] = __ldcg((const double2*)(hb + p * 4));

#pragma unroll
        for (int q = 0; q < 32; q++) {
            double2 hq = hbuf[q & 7];
            if (q + 8 < 32) hbuf[q & 7] = __ldcg((const double2*)(hb + (q + 8) * 4));
            ull hlo = __double_as_longlong(hq.x);
            ull hhi = __double_as_longlong(hq.y);
            const double2* wrow = (const double2*)(Ws + k0 + q * 4);
#pragma unroll
            for (int j = 0; j < 8; j++) {
                double2 wq = wrow[j * (HH / 4)];   // Ws[j][k0+4q..]: row = HH floats = HH/4 double2
                ffma2(acc[j], hlo, __double_as_longlong(wq.x));
                ffma2(acc[j], hhi, __double_as_longlong(wq.y));
            }
        }
        // store warp partials: Part[w][lane][jj], stride 9 (conflict-free: 9 coprime 32)
#pragma unroll
        for (int j = 0; j < 8; j++)
            Part[w * 288 + lane * 9 + j] = pairsum(acc[j]);
        __syncthreads();

        // reduce + tanh + store: thread handles output (b2, jj2)
        {
            float s = pre_base[(size_t)t * HH];
#pragma unroll
            for (int q = 0; q < 8; q++) s += Part[q * 288 + b2 * 9 + jj2];
            __stcg(&out_base[(size_t)t * HH], tanhf(s));
        }
        gridbar_ep(ep0 + t + 1);
    }
}

// ---------- head logsumexp (33 logits) ----------
__global__ void k_head() {
    int r = blockIdx.x * blockDim.x + threadIdx.x;
    if (r >= NROWS) return;
    int rr = g_rev[r >> 8] * 256 + (r & 255);
    const float* L = g_logits + (size_t)rr * 64;
    float m = -1e30f;
    for (int j = 0; j < 33; j++) m = fmaxf(m, L[j]);
    float se = 0.f;
    for (int j = 0; j < 33; j++) se += __expf(L[j] - m);
    g_hl[r] = m + logf(se);
}

// ---------- tail cluster 2 (19000 words x 16): warp=word-stripe, lane=row ----------
__global__ void __launch_bounds__(128)
k_tail2(const float* __restrict__ tw2, const int* __restrict__ target) {
    __shared__ float s_tl[32], s_m[4][32], s_s[4][32];
    int tid = threadIdx.x, warp = tid >> 5, lane = tid & 31;
    int r = blockIdx.x * 32 + lane;
    int tgt = target[r];
    int rr = g_rev[r >> 8] * 256 + (r & 255);
    const float4* pr = (const float4*)&g_logits[(size_t)rr * 64 + 36];
    float4 P0 = pr[0], P1 = pr[1], P2 = pr[2], P3 = pr[3];
    int wt = tgt - 1000;
    float m = -1e30f, se = 0.f;
    for (int w = warp; w < 19000; w += 4) {
        const float4* wr = (const float4*)(tw2 + (size_t)w * 16);
        float4 A = wr[0], B = wr[1], C = wr[2], D = wr[3];
        float l = P0.x * A.x; l = fmaf(P0.y, A.y, l); l = fmaf(P0.z, A.z, l); l = fmaf(P0.w, A.w, l);
        l = fmaf(P1.x, B.x, l); l = fmaf(P1.y, B.y, l); l = fmaf(P1.z, B.z, l); l = fmaf(P1.w, B.w, l);
        l = fmaf(P2.x, C.x, l); l = fmaf(P2.y, C.y, l); l = fmaf(P2.z, C.z, l); l = fmaf(P2.w, C.w, l);
        l = fmaf(P3.x, D.x, l); l = fmaf(P3.y, D.y, l); l = fmaf(P3.z, D.z, l); l = fmaf(P3.w, D.w, l);
        if (w == wt) s_tl[lane] = l;
        if (l > m) { se = se * __expf(m - l) + 1.f; m = l; }
        else       se += __expf(l - m);
    }
    s_m[warp][lane] = m; s_s[warp][lane] = se;
    __syncthreads();
    if (warp == 0) {
        float M = s_m[0][lane];
        for (int q = 1; q < 4; q++) M = fmaxf(M, s_m[q][lane]);
        float S = 0.f;
        for (int q = 0; q < 4; q++) S += s_s[q][lane] * __expf(s_m[q][lane] - M);
        if (tgt >= 1000) g_ct[r] = (M + logf(S)) - s_tl[lane];
    }
}

// ---------- tail clusters 0/1 (rare rows), early exit ----------
__global__ void __launch_bounds__(128)
k_tail01(const float* __restrict__ tp0, const float* __restrict__ tw0,
         const float* __restrict__ tp1, const float* __restrict__ tw1,
         const int* __restrict__ target) {
    int r = blockIdx.x;
    int tgt = target[r];
    if (tgt < 30 || tgt >= 1000) return;
    int lo, nw, d; const float *P, *W;
    if (tgt < 100) { lo = 30; nw = 70; d = 256; P = tp0; W = tw0; }
    else           { lo = 100; nw = 900; d = 64; P = tp1; W = tw1; }
    int tid = threadIdx.x, lane = tid & 31, warp = tid >> 5;
    int rr = g_rev[r >> 8] * 256 + (r & 255);
    __shared__ float xs[HH], proj[256], rm[128], rs[128], s_tl;
    const float* xr = g_h2 + (size_t)rr * HH;
    for (int i = tid; i < HH; i += 128) xs[i] = xr[i];
    __syncthreads();
    for (int p = warp; p < d; p += 4) {
        const float* wr = P + (size_t)p * HH;
        float s = 0.f;
        for (int k = lane; k < HH; k += 32) s = fmaf(xs[k], wr[k], s);
#pragma unroll
        for (int off = 16; off; off >>= 1) s += __shfl_xor_sync(0xffffffffu, s, off);
        if (lane == 0) proj[p] = s;
    }
    __syncthreads();
    float m = -1e30f, se = 0.f;
    for (int w = tid; w < nw; w += 128) {
        const float* wr = W + (size_t)w * d;
        float l = 0.f;
        for (int k = 0; k < d; k++) l = fmaf(proj[k], wr[k], l);
        if (w == tgt - lo) s_tl = l;
        if (l > m) { se = se * __expf(m - l) + 1.f; m = l; }
        else       se += __expf(l - m);
    }
    rm[tid] = m; rs[tid] = se;
    __syncthreads();
    if (tid == 0) {
        float M = -1e30f;
        for (int i = 0; i < 128; i++) M = fmaxf(M, rm[i]);
        float S = 0.f;
        for (int i = 0; i < 128; i++) S += rs[i] * __expf(rm[i] - M);
        g_ct[r] = (M + logf(S)) - s_tl;
    }
}

// ---------- assemble + deterministic sum ----------
__global__ void k_final(const int* __restrict__ target) {
    int r = blockIdx.x * blockDim.x + threadIdx.x;
    if (r >= NROWS) return;
    int tgt = target[r];
    int rr = g_rev[r >> 8] * 256 + (r & 255);
    float nll;
    if (tgt == 0) nll = 0.f;
    else if (tgt < 30) nll = g_hl[r] - g_logits[(size_t)rr * 64 + tgt];
    else {
        int ci = tgt < 100 ? 0 : (tgt < 1000 ? 1 : 2);
        nll = (g_hl[r] - g_logits[(size_t)rr * 64 + 30 + ci]) + g_ct[r];
    }
    g_nll[r] = nll;
}

__global__ void k_sum(float* __restrict__ out) {
    __shared__ float sd[256];
    int tid = threadIdx.x;
    float s = 0.f;
    for (int i = tid; i < NROWS; i += 256) s += g_nll[i];
    sd[tid] = s;
    __syncthreads();
    for (int st = 128; st; st >>= 1) {
        if (tid < st) sd[tid] += sd[tid + st];
        __syncthreads();
    }
    if (tid == 0) out[0] = sd[0];
}

extern "C" void kernel_launch(void* const* d_in, const int* in_sizes, int n_in,
                              void* d_out, int out_size) {
    const float* z      = (const float*)d_in[0];
    const float* emb    = (const float*)d_in[1];
    const float* l2h_w  = (const float*)d_in[2];
    const float* l2h_b  = (const float*)d_in[3];
    const float* r0wih  = (const float*)d_in[4];
    const float* r0whh  = (const float*)d_in[5];
    const float* r0bih  = (const float*)d_in[6];
    const float* r0bhh  = (const float*)d_in[7];
    const float* r1wih  = (const float*)d_in[8];
    const float* r1whh  = (const float*)d_in[9];
    const float* r1bih  = (const float*)d_in[10];
    const float* r1bhh  = (const float*)d_in[11];
    const float* head_w = (const float*)d_in[12];
    const float* tp0    = (const float*)d_in[13];
    const float* tw0    = (const float*)d_in[14];
    const float* tp1    = (const float*)d_in[15];
    const float* tw1    = (const float*)d_in[16];
    const float* tp2    = (const float*)d_in[17];
    const float* tw2    = (const float*)d_in[18];
    const int*   inp    = (const int*)d_in[19];
    const int*   target = (const int*)d_in[20];
    const int*   length = (const int*)d_in[21];
    float* out = (float*)d_out;

    float* gh1 = nullptr; float* gh2 = nullptr; float* gz = nullptr; float* gpw = nullptr;
    float* ghid = nullptr; float* gpre = nullptr; float* glog = nullptr;
    cudaGetSymbolAddress((void**)&gh1, g_h1);
    cudaGetSymbolAddress((void**)&gh2, g_h2);
    cudaGetSymbolAddress((void**)&gz, g_zero);
    cudaGetSymbolAddress((void**)&gpw, g_pw);
    cudaGetSymbolAddress((void**)&ghid, g_hidden);
    cudaGetSymbolAddress((void**)&gpre, g_pre);
    cudaGetSymbolAddress((void**)&glog, g_logits);

    k_prep<<<1, 32>>>(length);
    k_tok<<<NROWS / 256, 256>>>(inp);
    k_hidden<<<(2 * BB * HH) / 256, 256>>>(z, l2h_w, l2h_b);
    k_pack<<<64 * HH / 256, 256>>>(head_w, tp2);

    // layer 0 input pre-activations: emb[tok] @ W0ih^T + b
    k_sgemm<<<dim3(64, 16), 256>>>(emb, r0wih, r0bih, r0bhh, gpre, 512, HH, 1);
    k_rnn<<<NBLK, 256>>>(r0whh, gpre, ghid, gh1, 0u);
    // layer 1
    k_sgemm<<<dim3(64, 16), 256>>>(gh1, r1wih, r1bih, r1bhh, gpre, HH, HH, 0);
    k_rnn<<<NBLK, 256>>>(r1whh, gpre, ghid + BB * HH, gh2, (unsigned)SS);

    // packed head + tail2-proj logits: [8192 x 64]
    k_sgemm<<<dim3(64, 1), 256>>>(gh2, gpw, gz, gz, glog, HH, 64, 0);

    k_head<<<NROWS / 256, 256>>>();
    k_tail2<<<NROWS / 32, 128>>>(tw2, target);
    k_tail01<<<NROWS, 128>>>(tp0, tw0, tp1, tw1, target);
    k_final<<<NROWS / 256, 256>>>(target);
    k_sum<<<1, 256>>>(out);
    (void)in_sizes; (void)n_in; (void)out_size;
}

// round 7
// speedup vs baseline: 1.4479x; 1.0745x over previous
#include <cuda_runtime.h>
#include <math.h>

#define BB    32
#define SS    256
#define HH    1024
#define NROWS 8192
#define NBLK  128   // persistent RNN CTAs: each owns 8 j-columns, full k

typedef unsigned long long ull;

__device__ int    g_sorted[BB];
__device__ int    g_rev[BB];
__device__ int    g_tok[NROWS];
__device__ float  g_hidden[2 * BB * HH];
__device__ float  g_pre[NROWS * HH];
__device__ float  g_h1[(size_t)NROWS * HH];
__device__ float  g_h2[(size_t)NROWS * HH];
__device__ float  g_pw[64 * HH];          // packed: head_w rows 0..32, tp2 rows 36..51
__device__ float  g_logits[NROWS * 64];
__device__ float  g_hl[NROWS];
__device__ float  g_ct[NROWS];
__device__ float  g_nll[NROWS];
__device__ float  g_zero[64];
__device__ unsigned          g_cnt;
__device__ volatile unsigned g_flag;

// packed fp32x2 FMA: d = a*b + d  (per-lane IEEE fp32)
__device__ __forceinline__ void ffma2(ull& d, ull a, ull b) {
    asm("fma.rn.f32x2 %0, %1, %2, %0;" : "+l"(d) : "l"(a), "l"(b));
}
__device__ __forceinline__ ull packdup(float x) {
    ull r;
    asm("mov.b64 %0, {%1, %1};" : "=l"(r) : "r"(__float_as_uint(x)));
    return r;
}
__device__ __forceinline__ float pairsum(ull v) {
    float2 f = *reinterpret_cast<float2*>(&v);
    return f.x + f.y;
}

// ---------- prep ----------
__global__ void k_prep(const int* __restrict__ len) {
    if (threadIdx.x == 0) {
        g_cnt = 0; g_flag = 0;
        int idx[BB];
        for (int i = 0; i < BB; i++) idx[i] = i;
        for (int i = 1; i < BB; i++) {               // stable desc insertion sort
            int v = idx[i], lv = len[v], j = i - 1;
            while (j >= 0 && len[idx[j]] < lv) { idx[j + 1] = idx[j]; j--; }
            idx[j + 1] = v;
        }
        for (int p = 0; p < BB; p++) { g_sorted[p] = idx[p]; g_rev[idx[p]] = p; }
    }
}

__global__ void k_tok(const int* __restrict__ inp) {
    int r = blockIdx.x * blockDim.x + threadIdx.x;
    if (r < NROWS) g_tok[r] = inp[g_sorted[r >> 8] * SS + (r & 255)];
}

// hid = z @ l2h_w^T + b   (flat view == .view(2,B,H))
__global__ void k_hidden(const float* __restrict__ z, const float* __restrict__ w,
                         const float* __restrict__ b) {
    int o = blockIdx.x * blockDim.x + threadIdx.x;
    if (o >= 2 * BB * HH) return;
    const float* zr = z + (o >> 11) * 256;
    const float* wr = w + (size_t)(o & 2047) * 256;
    float acc = 0.f;
#pragma unroll 8
    for (int k = 0; k < 256; k++) acc = fmaf(zr[k], wr[k], acc);
    g_hidden[o] = acc + b[o & 2047];
}

__global__ void k_pack(const float* __restrict__ head_w, const float* __restrict__ tp2) {
    int i = blockIdx.x * blockDim.x + threadIdx.x;
    if (i >= 64 * HH) return;
    int row = i >> 10, c = i & 1023;
    float v = 0.f;
    if (row < 33)                 v = head_w[row * HH + c];
    else if (row >= 36 && row < 52) v = tp2[(row - 36) * HH + c];
    g_pw[i] = v;
}

// ---------- SGEMM (f32x2): C[n][m] = A[row(n)][:K] . Bw[m][:K] + b1[m]+b2[m] ----------
// BM=128 BN=64 BK=16, 256 thr, 8x4 reg tile (col-paired). gather!=0 => A row = g_tok[n]
__global__ void __launch_bounds__(256)
k_sgemm(const float* __restrict__ A, const float* __restrict__ Bw,
        const float* __restrict__ b1, const float* __restrict__ b2,
        float* __restrict__ C, int K, int M, int gather) {
    __shared__ __align__(16) float As[16][128];
    __shared__ __align__(16) float Bs[16][64];
    int tid = threadIdx.x, tx = tid & 15, ty = tid >> 4;
    int n0 = blockIdx.x * 128, m0 = blockIdx.y * 64;
    ull acc2[8][2];
#pragma unroll
    for (int r = 0; r < 8; r++) { acc2[r][0] = 0ull; acc2[r][1] = 0ull; }

    for (int k0 = 0; k0 < K; k0 += 16) {
#pragma unroll
        for (int i = 0; i < 2; i++) {
            int id = tid * 2 + i, r = id >> 2, kq = (id & 3) * 4;
            int grow = n0 + r;
            int arow = gather ? g_tok[grow] : grow;
            float4 v = *(const float4*)(A + (size_t)arow * K + k0 + kq);
            As[kq][r] = v.x; As[kq + 1][r] = v.y; As[kq + 2][r] = v.z; As[kq + 3][r] = v.w;
        }
        {
            int m = tid >> 2, kq = (tid & 3) * 4;
            float4 v = *(const float4*)(Bw + (size_t)(m0 + m) * K + k0 + kq);
            Bs[kq][m] = v.x; Bs[kq + 1][m] = v.y; Bs[kq + 2][m] = v.z; Bs[kq + 3][m] = v.w;
        }
        __syncthreads();
#pragma unroll
        for (int k = 0; k < 16; k++) {
            float4 a0 = *(float4*)&As[k][ty * 8];
            float4 a1 = *(float4*)&As[k][ty * 8 + 4];
            const ull* bp = (const ull*)&Bs[k][tx * 4];
            ull b01 = bp[0], b23 = bp[1];
            float a[8] = {a0.x, a0.y, a0.z, a0.w, a1.x, a1.y, a1.z, a1.w};
#pragma unroll
            for (int r = 0; r < 8; r++) {
                ull ap = packdup(a[r]);
                ffma2(acc2[r][0], ap, b01);
                ffma2(acc2[r][1], ap, b23);
            }
        }
        __syncthreads();
    }
    float bias[4];
#pragma unroll
    for (int c = 0; c < 4; c++) { int m = m0 + tx * 4 + c; bias[c] = b1[m] + b2[m]; }
#pragma unroll
    for (int r = 0; r < 8; r++) {
        int n = n0 + ty * 8 + r;
        float2 p0 = *(float2*)&acc2[r][0];
        float2 p1 = *(float2*)&acc2[r][1];
        float4 v = make_float4(p0.x + bias[0], p0.y + bias[1],
                               p1.x + bias[2], p1.y + bias[3]);
        *(float4*)(C + (size_t)n * M + m0 + tx * 4) = v;
    }
}

// ---------- monotonic-epoch grid barrier ----------
__device__ __forceinline__ void gridbar_ep(unsigned ep) {
    __syncthreads();
    if (threadIdx.x == 0) {
        __threadfence();
        unsigned old = atomicAdd(&g_cnt, 1u);
        if (old == ep * NBLK - 1) {
            g_flag = ep;
            __threadfence();
        } else {
            while (g_flag < ep) __nanosleep(32);
            __threadfence();
        }
    }
    __syncthreads();
}

// ---------- persistent RNN layer: 128 CTAs x 256 thr, COALESCED h loads ----------
// CTA owns 8 j-cols over full k. Warp w owns batch rows 4w..4w+3; lane l reads
// k = 128q + 4l (contiguous per warp instruction, nL=4). W from smem LDS.128,
// reused across 4 b. Cross-lane reduce via padded smem transpose. 1 barrier/step.
__global__ void __launch_bounds__(256, 1)
k_rnn(const float* __restrict__ Whh, const float* __restrict__ pre,
      const float* __restrict__ h0, float* __restrict__ hseq, unsigned ep0) {
    extern __shared__ float sm[];
    float* Ws = sm;              // [8][1024]
    float* Part = sm + 8 * HH;   // [32][257] (lane-major, pad 257)
    int tid = threadIdx.x, bid = blockIdx.x;
    int w = tid >> 5, lane = tid & 31;
    int j0 = bid * 8;

    {   // load W slice: 8 rows x 1024, coalesced float4
        const float4* src = (const float4*)(Whh + (size_t)j0 * HH);
        float4* dst = (float4*)Ws;
        for (int i = tid; i < 8 * 256; i += 256) dst[i] = src[i];
    }
    __syncthreads();

    int b0 = w * 4;              // this warp's 4 batch rows
    int kl = lane * 4;           // lane's k offset within each 512B chunk
    int b2 = tid >> 3, jj2 = tid & 7;    // reduce-phase output (b, j)
    const float* pre_base = pre + ((size_t)b2 * SS) * HH + j0 + jj2;
    float* out_base = hseq + ((size_t)b2 * SS) * HH + j0 + jj2;

    for (int t = 0; t < SS; t++) {
        const float* hp[4];
#pragma unroll
        for (int bl = 0; bl < 4; bl++)
            hp[bl] = (t == 0)
                ? (h0 + (b0 + bl) * HH + kl)
                : (hseq + ((size_t)(b0 + bl) * SS + (t - 1)) * HH + kl);

        ull acc[4][8];
#pragma unroll
        for (int bl = 0; bl < 4; bl++)
#pragma unroll
            for (int j = 0; j < 8; j++) acc[bl][j] = 0ull;

        ulonglong2 hq[2][4];
#pragma unroll
        for (int bl = 0; bl < 4; bl++)
            hq[0][bl] = __ldcg((const ulonglong2*)hp[bl]);

#pragma unroll
        for (int q = 0; q < 8; q++) {
            if (q + 1 < 8) {
#pragma unroll
                for (int bl = 0; bl < 4; bl++)
                    hq[(q + 1) & 1][bl] =
                        __ldcg((const ulonglong2*)(hp[bl] + (q + 1) * 128));
            }
#pragma unroll
            for (int j = 0; j < 8; j++) {
                ulonglong2 wv = *(const ulonglong2*)(Ws + j * HH + q * 128 + kl);
#pragma unroll
                for (int bl = 0; bl < 4; bl++) {
                    ffma2(acc[bl][j], hq[q & 1][bl].x, wv.x);
                    ffma2(acc[bl][j], hq[q & 1][bl].y, wv.y);
                }
            }
        }
        // transpose partials into smem: Part[lane][32w + 8bl + j], stride 257
#pragma unroll
        for (int bl = 0; bl < 4; bl++)
#pragma unroll
            for (int j = 0; j < 8; j++)
                Part[lane * 257 + w * 32 + bl * 8 + j] = pairsum(acc[bl][j]);
        __syncthreads();

        // reduce 32 lanes + pre, tanh, coalesced store: thread t -> output (b2, jj2)
        {
            float s = pre_base[(size_t)t * HH];
#pragma unroll
            for (int l = 0; l < 32; l++) s += Part[l * 257 + tid];
            __stcg(&out_base[(size_t)t * HH], tanhf(s));
        }
        gridbar_ep(ep0 + t + 1);
    }
}

// ---------- head logsumexp (33 logits) ----------
__global__ void k_head() {
    int r = blockIdx.x * blockDim.x + threadIdx.x;
    if (r >= NROWS) return;
    int rr = g_rev[r >> 8] * 256 + (r & 255);
    const float* L = g_logits + (size_t)rr * 64;
    float m = -1e30f;
    for (int j = 0; j < 33; j++) m = fmaxf(m, L[j]);
    float se = 0.f;
    for (int j = 0; j < 33; j++) se += __expf(L[j] - m);
    g_hl[r] = m + logf(se);
}

// ---------- tail cluster 2 (19000 words x 16): warp=word-stripe, lane=row ----------
__global__ void __launch_bounds__(128)
k_tail2(const float* __restrict__ tw2, const int* __restrict__ target) {
    __shared__ float s_tl[32], s_m[4][32], s_s[4][32];
    int tid = threadIdx.x, warp = tid >> 5, lane = tid & 31;
    int r = blockIdx.x * 32 + lane;
    int tgt = target[r];
    int rr = g_rev[r >> 8] * 256 + (r & 255);
    const ulonglong2* pr = (const ulonglong2*)&g_logits[(size_t)rr * 64 + 36];
    ulonglong2 p0 = pr[0], p1 = pr[1], p2 = pr[2], p3 = pr[3];
    int wt = tgt - 1000;
    float m = -1e30f, se = 0.f;
    for (int w = warp; w < 19000; w += 4) {
        const ulonglong2* wr = (const ulonglong2*)(tw2 + (size_t)w * 16);
        ulonglong2 q0 = wr[0], q1 = wr[1], q2 = wr[2], q3 = wr[3];
        ull a = 0ull;
        ffma2(a, p0.x, q0.x); ffma2(a, p0.y, q0.y);
        ffma2(a, p1.x, q1.x); ffma2(a, p1.y, q1.y);
        ffma2(a, p2.x, q2.x); ffma2(a, p2.y, q2.y);
        ffma2(a, p3.x, q3.x); ffma2(a, p3.y, q3.y);
        float l = pairsum(a);
        if (w == wt) s_tl[lane] = l;
        if (l > m) { se = se * __expf(m - l) + 1.f; m = l; }
        else       se += __expf(l - m);
    }
    s_m[warp][lane] = m; s_s[warp][lane] = se;
    __syncthreads();
    if (warp == 0) {
        float M = s_m[0][lane];
        for (int q = 1; q < 4; q++) M = fmaxf(M, s_m[q][lane]);
        float S = 0.f;
        for (int q = 0; q < 4; q++) S += s_s[q][lane] * __expf(s_m[q][lane] - M);
        if (tgt >= 1000) g_ct[r] = (M + logf(S)) - s_tl[lane];
    }
}

// ---------- tail clusters 0/1 (rare rows), early exit ----------
__global__ void __launch_bounds__(128)
k_tail01(const float* __restrict__ tp0, const float* __restrict__ tw0,
         const float* __restrict__ tp1, const float* __restrict__ tw1,
         const int* __restrict__ target) {
    int r = blockIdx.x;
    int tgt = target[r];
    if (tgt < 30 || tgt >= 1000) return;
    int lo, nw, d; const float *P, *W;
    if (tgt < 100) { lo = 30; nw = 70; d = 256; P = tp0; W = tw0; }
    else           { lo = 100; nw = 900; d = 64; P = tp1; W = tw1; }
    int tid = threadIdx.x, lane = tid & 31, warp = tid >> 5;
    int rr = g_rev[r >> 8] * 256 + (r & 255);
    __shared__ float xs[HH], proj[256], rm[128], rs[128], s_tl;
    const float* xr = g_h2 + (size_t)rr * HH;
    for (int i = tid; i < HH; i += 128) xs[i] = xr[i];
    __syncthreads();
    for (int p = warp; p < d; p += 4) {
        const float* wr = P + (size_t)p * HH;
        float s = 0.f;
        for (int k = lane; k < HH; k += 32) s = fmaf(xs[k], wr[k], s);
#pragma unroll
        for (int off = 16; off; off >>= 1) s += __shfl_xor_sync(0xffffffffu, s, off);
        if (lane == 0) proj[p] = s;
    }
    __syncthreads();
    float m = -1e30f, se = 0.f;
    for (int w = tid; w < nw; w += 128) {
        const float* wr = W + (size_t)w * d;
        float l = 0.f;
        for (int k = 0; k < d; k++) l = fmaf(proj[k], wr[k], l);
        if (w == tgt - lo) s_tl = l;
        if (l > m) { se = se * __expf(m - l) + 1.f; m = l; }
        else       se += __expf(l - m);
    }
    rm[tid] = m; rs[tid] = se;
    __syncthreads();
    if (tid == 0) {
        float M = -1e30f;
        for (int i = 0; i < 128; i++) M = fmaxf(M, rm[i]);
        float S = 0.f;
        for (int i = 0; i < 128; i++) S += rs[i] * __expf(rm[i] - M);
        g_ct[r] = (M + logf(S)) - s_tl;
    }
}

// ---------- assemble + deterministic sum ----------
__global__ void k_final(const int* __restrict__ target) {
    int r = blockIdx.x * blockDim.x + threadIdx.x;
    if (r >= NROWS) return;
    int tgt = target[r];
    int rr = g_rev[r >> 8] * 256 + (r & 255);
    float nll;
    if (tgt == 0) nll = 0.f;
    else if (tgt < 30) nll = g_hl[r] - g_logits[(size_t)rr * 64 + tgt];
    else {
        int ci = tgt < 100 ? 0 : (tgt < 1000 ? 1 : 2);
        nll = (g_hl[r] - g_logits[(size_t)rr * 64 + 30 + ci]) + g_ct[r];
    }
    g_nll[r] = nll;
}

__global__ void k_sum(float* __restrict__ out) {
    __shared__ float sd[256];
    int tid = threadIdx.x;
    float s = 0.f;
    for (int i = tid; i < NROWS; i += 256) s += g_nll[i];
    sd[tid] = s;
    __syncthreads();
    for (int st = 128; st; st >>= 1) {
        if (tid < st) sd[tid] += sd[tid + st];
        __syncthreads();
    }
    if (tid == 0) out[0] = sd[0];
}

#define RNN_SMEM ((8 * HH + 32 * 257) * 4)

extern "C" void kernel_launch(void* const* d_in, const int* in_sizes, int n_in,
                              void* d_out, int out_size) {
    const float* z      = (const float*)d_in[0];
    const float* emb    = (const float*)d_in[1];
    const float* l2h_w  = (const float*)d_in[2];
    const float* l2h_b  = (const float*)d_in[3];
    const float* r0wih  = (const float*)d_in[4];
    const float* r0whh  = (const float*)d_in[5];
    const float* r0bih  = (const float*)d_in[6];
    const float* r0bhh  = (const float*)d_in[7];
    const float* r1wih  = (const float*)d_in[8];
    const float* r1whh  = (const float*)d_in[9];
    const float* r1bih  = (const float*)d_in[10];
    const float* r1bhh  = (const float*)d_in[11];
    const float* head_w = (const float*)d_in[12];
    const float* tp0    = (const float*)d_in[13];
    const float* tw0    = (const float*)d_in[14];
    const float* tp1    = (const float*)d_in[15];
    const float* tw1    = (const float*)d_in[16];
    const float* tp2    = (const float*)d_in[17];
    const float* tw2    = (const float*)d_in[18];
    const int*   inp    = (const int*)d_in[19];
    const int*   target = (const int*)d_in[20];
    const int*   length = (const int*)d_in[21];
    float* out = (float*)d_out;

    float* gh1 = nullptr; float* gh2 = nullptr; float* gz = nullptr; float* gpw = nullptr;
    float* ghid = nullptr; float* gpre = nullptr; float* glog = nullptr;
    cudaGetSymbolAddress((void**)&gh1, g_h1);
    cudaGetSymbolAddress((void**)&gh2, g_h2);
    cudaGetSymbolAddress((void**)&gz, g_zero);
    cudaGetSymbolAddress((void**)&gpw, g_pw);
    cudaGetSymbolAddress((void**)&ghid, g_hidden);
    cudaGetSymbolAddress((void**)&gpre, g_pre);
    cudaGetSymbolAddress((void**)&glog, g_logits);

    cudaFuncSetAttribute(k_rnn, cudaFuncAttributeMaxDynamicSharedMemorySize, RNN_SMEM);

    k_prep<<<1, 32>>>(length);
    k_tok<<<NROWS / 256, 256>>>(inp);
    k_hidden<<<(2 * BB * HH) / 256, 256>>>(z, l2h_w, l2h_b);
    k_pack<<<64 * HH / 256, 256>>>(head_w, tp2);

    // layer 0 input pre-activations: emb[tok] @ W0ih^T + b
    k_sgemm<<<dim3(64, 16), 256>>>(emb, r0wih, r0bih, r0bhh, gpre, 512, HH, 1);
    k_rnn<<<NBLK, 256, RNN_SMEM>>>(r0whh, gpre, ghid, gh1, 0u);
    // layer 1
    k_sgemm<<<dim3(64, 16), 256>>>(gh1, r1wih, r1bih, r1bhh, gpre, HH, HH, 0);
    k_rnn<<<NBLK, 256, RNN_SMEM>>>(r1whh, gpre, ghid + BB * HH, gh2, (unsigned)SS);

    // packed head + tail2-proj logits: [8192 x 64]
    k_sgemm<<<dim3(64, 1), 256>>>(gh2, gpw, gz, gz, glog, HH, 64, 0);

    k_head<<<NROWS / 256, 256>>>();
    k_tail2<<<NROWS / 32, 128>>>(tw2, target);
    k_tail01<<<NROWS, 128>>>(tp0, tw0, tp1, tw1, target);
    k_final<<<NROWS / 256, 256>>>(target);
    k_sum<<<1, 256>>>(out);
    (void)in_sizes; (void)n_in; (void)out_size;
}

// round 8
// speedup vs baseline: 2.1554x; 1.4886x over previous
#include <cuda_runtime.h>
#include <math.h>

#define BB    32
#define SS    256
#define HH    1024
#define NROWS 8192
#define NBLK  128

typedef unsigned long long ull;

__device__ int    g_sorted[BB];
__device__ int    g_rev[BB];
__device__ int    g_tok[NROWS];
__device__ float  g_hidden[2 * BB * HH];
__device__ float  g_pre[NROWS * HH];
__device__ float  g_h1[(size_t)NROWS * HH];
__device__ float  g_h2[(size_t)NROWS * HH];
__device__ float  g_pw[64 * HH];          // packed: head_w rows 0..32, tp2 rows 36..51
__device__ float  g_logits[NROWS * 64];
__device__ float  g_hl[NROWS];
__device__ float  g_ct[NROWS];
__device__ float  g_nll[NROWS];
__device__ float  g_zero[64];
__device__ unsigned          g_leaf[16 * 32];   // leaf counters, 128B apart
__device__ unsigned          g_root;
__device__ volatile unsigned g_flag;

// packed fp32x2 FMA: d = a*b + d  (per-lane IEEE fp32)
__device__ __forceinline__ void ffma2(ull& d, ull a, ull b) {
    asm("fma.rn.f32x2 %0, %1, %2, %0;" : "+l"(d) : "l"(a), "l"(b));
}
__device__ __forceinline__ ull packdup(float x) {
    ull r;
    asm("mov.b64 %0, {%1, %1};" : "=l"(r) : "r"(__float_as_uint(x)));
    return r;
}
__device__ __forceinline__ float pairsum(ull v) {
    float2 f = *reinterpret_cast<float2*>(&v);
    return f.x + f.y;
}

// ---------- prep ----------
__global__ void k_prep(const int* __restrict__ len) {
    if (threadIdx.x == 0) {
        g_root = 0; g_flag = 0;
        for (int i = 0; i < 16 * 32; i++) g_leaf[i] = 0;
        int idx[BB];
        for (int i = 0; i < BB; i++) idx[i] = i;
        for (int i = 1; i < BB; i++) {               // stable desc insertion sort
            int v = idx[i], lv = len[v], j = i - 1;
            while (j >= 0 && len[idx[j]] < lv) { idx[j + 1] = idx[j]; j--; }
            idx[j + 1] = v;
        }
        for (int p = 0; p < BB; p++) { g_sorted[p] = idx[p]; g_rev[idx[p]] = p; }
    }
}

__global__ void k_tok(const int* __restrict__ inp) {
    int r = blockIdx.x * blockDim.x + threadIdx.x;
    if (r < NROWS) g_tok[r] = inp[g_sorted[r >> 8] * SS + (r & 255)];
}

// hid = z @ l2h_w^T + b   (flat view == .view(2,B,H))
__global__ void k_hidden(const float* __restrict__ z, const float* __restrict__ w,
                         const float* __restrict__ b) {
    int o = blockIdx.x * blockDim.x + threadIdx.x;
    if (o >= 2 * BB * HH) return;
    const float* zr = z + (o >> 11) * 256;
    const float* wr = w + (size_t)(o & 2047) * 256;
    float acc = 0.f;
#pragma unroll 8
    for (int k = 0; k < 256; k++) acc = fmaf(zr[k], wr[k], acc);
    g_hidden[o] = acc + b[o & 2047];
}

__global__ void k_pack(const float* __restrict__ head_w, const float* __restrict__ tp2) {
    int i = blockIdx.x * blockDim.x + threadIdx.x;
    if (i >= 64 * HH) return;
    int row = i >> 10, c = i & 1023;
    float v = 0.f;
    if (row < 33)                 v = head_w[row * HH + c];
    else if (row >= 36 && row < 52) v = tp2[(row - 36) * HH + c];
    g_pw[i] = v;
}

// ---------- SGEMM (f32x2): C[n][m] = A[row(n)][:K] . Bw[m][:K] + b1[m]+b2[m] ----------
__global__ void __launch_bounds__(256)
k_sgemm(const float* __restrict__ A, const float* __restrict__ Bw,
        const float* __restrict__ b1, const float* __restrict__ b2,
        float* __restrict__ C, int K, int M, int gather) {
    __shared__ __align__(16) float As[16][128];
    __shared__ __align__(16) float Bs[16][64];
    int tid = threadIdx.x, tx = tid & 15, ty = tid >> 4;
    int n0 = blockIdx.x * 128, m0 = blockIdx.y * 64;
    ull acc2[8][2];
#pragma unroll
    for (int r = 0; r < 8; r++) { acc2[r][0] = 0ull; acc2[r][1] = 0ull; }

    for (int k0 = 0; k0 < K; k0 += 16) {
#pragma unroll
        for (int i = 0; i < 2; i++) {
            int id = tid * 2 + i, r = id >> 2, kq = (id & 3) * 4;
            int grow = n0 + r;
            int arow = gather ? g_tok[grow] : grow;
            float4 v = *(const float4*)(A + (size_t)arow * K + k0 + kq);
            As[kq][r] = v.x; As[kq + 1][r] = v.y; As[kq + 2][r] = v.z; As[kq + 3][r] = v.w;
        }
        {
            int m = tid >> 2, kq = (tid & 3) * 4;
            float4 v = *(const float4*)(Bw + (size_t)(m0 + m) * K + k0 + kq);
            Bs[kq][m] = v.x; Bs[kq + 1][m] = v.y; Bs[kq + 2][m] = v.z; Bs[kq + 3][m] = v.w;
        }
        __syncthreads();
#pragma unroll
        for (int k = 0; k < 16; k++) {
            float4 a0 = *(float4*)&As[k][ty * 8];
            float4 a1 = *(float4*)&As[k][ty * 8 + 4];
            const ull* bp = (const ull*)&Bs[k][tx * 4];
            ull b01 = bp[0], b23 = bp[1];
            float a[8] = {a0.x, a0.y, a0.z, a0.w, a1.x, a1.y, a1.z, a1.w};
#pragma unroll
            for (int r = 0; r < 8; r++) {
                ull ap = packdup(a[r]);
                ffma2(acc2[r][0], ap, b01);
                ffma2(acc2[r][1], ap, b23);
            }
        }
        __syncthreads();
    }
    float bias[4];
#pragma unroll
    for (int c = 0; c < 4; c++) { int m = m0 + tx * 4 + c; bias[c] = b1[m] + b2[m]; }
#pragma unroll
    for (int r = 0; r < 8; r++) {
        int n = n0 + ty * 8 + r;
        float2 p0 = *(float2*)&acc2[r][0];
        float2 p1 = *(float2*)&acc2[r][1];
        float4 v = make_float4(p0.x + bias[0], p0.y + bias[1],
                               p1.x + bias[2], p1.y + bias[3]);
        *(float4*)(C + (size_t)n * M + m0 + tx * 4) = v;
    }
}

// ---------- tree grid barrier (monotonic epochs) ----------
__device__ __forceinline__ void gridbar_ep(unsigned ep, int bid) {
    __syncthreads();
    if (threadIdx.x == 0) {
        __threadfence();
        unsigned old = atomicAdd(&g_leaf[(bid >> 3) * 32], 1u);
        if (old == ep * 8u - 1u) {
            unsigned r = atomicAdd(&g_root, 1u);
            if (r == ep * 16u - 1u) {
                __threadfence();
                g_flag = ep;
            } else {
                while (g_flag < ep) __nanosleep(16);
            }
        } else {
            while (g_flag < ep) __nanosleep(16);
        }
        __threadfence();
    }
    __syncthreads();
}

// matvec accumulate: acc[bl][j] += dot(Wsm[j][:], h[bl][:]) over this thread's k
__device__ __forceinline__ void matvec_acc(ull acc[4][8], const float* Wsm,
                                           const float* h0p, const float* h1p,
                                           const float* h2p, const float* h3p, int kl) {
    const float* hp[4] = {h0p, h1p, h2p, h3p};
    ulonglong2 hq[2][4];
#pragma unroll
    for (int bl = 0; bl < 4; bl++) hq[0][bl] = __ldcg((const ulonglong2*)hp[bl]);
#pragma unroll
    for (int q = 0; q < 8; q++) {
        if (q + 1 < 8) {
#pragma unroll
            for (int bl = 0; bl < 4; bl++)
                hq[(q + 1) & 1][bl] = __ldcg((const ulonglong2*)(hp[bl] + (q + 1) * 128));
        }
#pragma unroll
        for (int j = 0; j < 8; j++) {
            ulonglong2 wv = *(const ulonglong2*)(Wsm + j * HH + q * 128 + kl);
#pragma unroll
            for (int bl = 0; bl < 4; bl++) {
                ffma2(acc[bl][j], hq[q & 1][bl].x, wv.x);
                ffma2(acc[bl][j], hq[q & 1][bl].y, wv.y);
            }
        }
    }
}

// ---------- fused 2-layer persistent RNN ----------
// 128 CTAs x 256 thr; CTA owns j0..j0+7 of BOTH layers.
// Step s: L0 computes h1(s) (s<256); L1 computes h2(s-1) (s>=1) with the
// W1ih·h1(s-1) input matvec folded in. ONE grid barrier per step (257 total).
__global__ void __launch_bounds__(256, 1)
k_rnn_fused(const float* __restrict__ W0hh, const float* __restrict__ W1ih,
            const float* __restrict__ W1hh, const float* __restrict__ pre1,
            const float* __restrict__ b1ih, const float* __restrict__ b1hh,
            const float* __restrict__ hid,
            float* __restrict__ h1seq, float* __restrict__ h2seq) {
    extern __shared__ float sm[];
    float* Ws0 = sm;                 // [8][1024]
    float* Wsi = sm + 8 * HH;
    float* Wsh = sm + 16 * HH;
    float* Part0 = sm + 24 * HH;     // [32][257]
    float* Part1 = Part0 + 32 * 257;
    int tid = threadIdx.x, bid = blockIdx.x;
    int w = tid >> 5, lane = tid & 31;
    int j0 = bid * 8;

    {   // load 3 W slices, coalesced float4
        const float4* s0 = (const float4*)(W0hh + (size_t)j0 * HH);
        const float4* s1 = (const float4*)(W1ih + (size_t)j0 * HH);
        const float4* s2 = (const float4*)(W1hh + (size_t)j0 * HH);
        float4* d0 = (float4*)Ws0; float4* d1 = (float4*)Wsi; float4* d2 = (float4*)Wsh;
        for (int i = tid; i < 8 * 256; i += 256) { d0[i] = s0[i]; d1[i] = s1[i]; d2[i] = s2[i]; }
    }
    __syncthreads();

    int b0 = w * 4;              // warp's 4 batch rows
    int kl = lane * 4;           // lane's k offset
    int b2 = tid >> 3, jj2 = tid & 7;   // reduce-phase output (b, j)
    float bias1v = b1ih[j0 + jj2] + b1hh[j0 + jj2];
    const float* pre_base = pre1 + ((size_t)b2 * SS) * HH + j0 + jj2;
    float* out1 = h1seq + ((size_t)b2 * SS) * HH + j0 + jj2;
    float* out2 = h2seq + ((size_t)b2 * SS) * HH + j0 + jj2;
    const float* hid0 = hid;
    const float* hid1 = hid + BB * HH;

    ull acc[4][8];

    for (int s = 0; s <= SS; s++) {
        float pre_v = 0.f;
        if (s < SS) pre_v = __ldcg(&pre_base[(size_t)s * HH]);   // prefetch early

        if (s < SS) {   // layer 0: h1(s)
#pragma unroll
            for (int bl = 0; bl < 4; bl++)
#pragma unroll
                for (int j = 0; j < 8; j++) acc[bl][j] = 0ull;
            const float* p0; const float* p1; const float* p2; const float* p3;
            if (s == 0) {
                p0 = hid0 + (b0 + 0) * HH + kl; p1 = hid0 + (b0 + 1) * HH + kl;
                p2 = hid0 + (b0 + 2) * HH + kl; p3 = hid0 + (b0 + 3) * HH + kl;
            } else {
                p0 = h1seq + ((size_t)(b0 + 0) * SS + s - 1) * HH + kl;
                p1 = h1seq + ((size_t)(b0 + 1) * SS + s - 1) * HH + kl;
                p2 = h1seq + ((size_t)(b0 + 2) * SS + s - 1) * HH + kl;
                p3 = h1seq + ((size_t)(b0 + 3) * SS + s - 1) * HH + kl;
            }
            matvec_acc(acc, Ws0, p0, p1, p2, p3, kl);
#pragma unroll
            for (int bl = 0; bl < 4; bl++)
#pragma unroll
                for (int j = 0; j < 8; j++)
                    Part0[lane * 257 + w * 32 + bl * 8 + j] = pairsum(acc[bl][j]);
        }

        if (s >= 1) {   // layer 1: h2(s-1) = tanh(b1 + W1ih h1(s-1) + W1hh h2(s-2))
#pragma unroll
            for (int bl = 0; bl < 4; bl++)
#pragma unroll
                for (int j = 0; j < 8; j++) acc[bl][j] = 0ull;
            const float* q0 = h1seq + ((size_t)(b0 + 0) * SS + s - 1) * HH + kl;
            const float* q1 = h1seq + ((size_t)(b0 + 1) * SS + s - 1) * HH + kl;
            const float* q2 = h1seq + ((size_t)(b0 + 2) * SS + s - 1) * HH + kl;
            const float* q3 = h1seq + ((size_t)(b0 + 3) * SS + s - 1) * HH + kl;
            matvec_acc(acc, Wsi, q0, q1, q2, q3, kl);
            const float* r0; const float* r1; const float* r2; const float* r3;
            if (s == 1) {
                r0 = hid1 + (b0 + 0) * HH + kl; r1 = hid1 + (b0 + 1) * HH + kl;
                r2 = hid1 + (b0 + 2) * HH + kl; r3 = hid1 + (b0 + 3) * HH + kl;
            } else {
                r0 = h2seq + ((size_t)(b0 + 0) * SS + s - 2) * HH + kl;
                r1 = h2seq + ((size_t)(b0 + 1) * SS + s - 2) * HH + kl;
                r2 = h2seq + ((size_t)(b0 + 2) * SS + s - 2) * HH + kl;
                r3 = h2seq + ((size_t)(b0 + 3) * SS + s - 2) * HH + kl;
            }
            matvec_acc(acc, Wsh, r0, r1, r2, r3, kl);
#pragma unroll
            for (int bl = 0; bl < 4; bl++)
#pragma unroll
                for (int j = 0; j < 8; j++)
                    Part1[lane * 257 + w * 32 + bl * 8 + j] = pairsum(acc[bl][j]);
        }
        __syncthreads();

        if (s < SS) {
            float sum = pre_v;
#pragma unroll
            for (int l = 0; l < 32; l++) sum += Part0[l * 257 + tid];
            __stcg(&out1[(size_t)s * HH], tanhf(sum));
        }
        if (s >= 1) {
            float sum = bias1v;
#pragma unroll
            for (int l = 0; l < 32; l++) sum += Part1[l * 257 + tid];
            __stcg(&out2[(size_t)(s - 1) * HH], tanhf(sum));
        }
        gridbar_ep((unsigned)(s + 1), bid);
    }
}

// ---------- head logsumexp (33 logits) ----------
__global__ void k_head() {
    int r = blockIdx.x * blockDim.x + threadIdx.x;
    if (r >= NROWS) return;
    int rr = g_rev[r >> 8] * 256 + (r & 255);
    const float* L = g_logits + (size_t)rr * 64;
    float m = -1e30f;
    for (int j = 0; j < 33; j++) m = fmaxf(m, L[j]);
    float se = 0.f;
    for (int j = 0; j < 33; j++) se += __expf(L[j] - m);
    g_hl[r] = m + logf(se);
}

// ---------- tail cluster 2 (19000 words x 16): warp=word-stripe, lane=row ----------
__global__ void __launch_bounds__(128)
k_tail2(const float* __restrict__ tw2, const int* __restrict__ target) {
    __shared__ float s_tl[32], s_m[4][32], s_s[4][32];
    int tid = threadIdx.x, warp = tid >> 5, lane = tid & 31;
    int r = blockIdx.x * 32 + lane;
    int tgt = target[r];
    int rr = g_rev[r >> 8] * 256 + (r & 255);
    const ulonglong2* pr = (const ulonglong2*)&g_logits[(size_t)rr * 64 + 36];
    ulonglong2 p0 = pr[0], p1 = pr[1], p2 = pr[2], p3 = pr[3];
    int wt = tgt - 1000;
    float m = -1e30f, se = 0.f;
    for (int w = warp; w < 19000; w += 4) {
        const ulonglong2* wr = (const ulonglong2*)(tw2 + (size_t)w * 16);
        ulonglong2 q0 = wr[0], q1 = wr[1], q2 = wr[2], q3 = wr[3];
        ull a = 0ull;
        ffma2(a, p0.x, q0.x); ffma2(a, p0.y, q0.y);
        ffma2(a, p1.x, q1.x); ffma2(a, p1.y, q1.y);
        ffma2(a, p2.x, q2.x); ffma2(a, p2.y, q2.y);
        ffma2(a, p3.x, q3.x); ffma2(a, p3.y, q3.y);
        float l = pairsum(a);
        if (w == wt) s_tl[lane] = l;
        if (l > m) { se = se * __expf(m - l) + 1.f; m = l; }
        else       se += __expf(l - m);
    }
    s_m[warp][lane] = m; s_s[warp][lane] = se;
    __syncthreads();
    if (warp == 0) {
        float M = s_m[0][lane];
        for (int q = 1; q < 4; q++) M = fmaxf(M, s_m[q][lane]);
        float S = 0.f;
        for (int q = 0; q < 4; q++) S += s_s[q][lane] * __expf(s_m[q][lane] - M);
        if (tgt >= 1000) g_ct[r] = (M + logf(S)) - s_tl[lane];
    }
}

// ---------- tail clusters 0/1 (rare rows), early exit ----------
__global__ void __launch_bounds__(128)
k_tail01(const float* __restrict__ tp0, const float* __restrict__ tw0,
         const float* __restrict__ tp1, const float* __restrict__ tw1,
         const int* __restrict__ target) {
    int r = blockIdx.x;
    int tgt = target[r];
    if (tgt < 30 || tgt >= 1000) return;
    int lo, nw, d; const float *P, *W;
    if (tgt < 100) { lo = 30; nw = 70; d = 256; P = tp0; W = tw0; }
    else           { lo = 100; nw = 900; d = 64; P = tp1; W = tw1; }
    int tid = threadIdx.x, lane = tid & 31, warp = tid >> 5;
    int rr = g_rev[r >> 8] * 256 + (r & 255);
    __shared__ float xs[HH], proj[256], rm[128], rs[128], s_tl;
    const float* xr = g_h2 + (size_t)rr * HH;
    for (int i = tid; i < HH; i += 128) xs[i] = xr[i];
    __syncthreads();
    for (int p = warp; p < d; p += 4) {
        const float* wr = P + (size_t)p * HH;
        float s = 0.f;
        for (int k = lane; k < HH; k += 32) s = fmaf(xs[k], wr[k], s);
#pragma unroll
        for (int off = 16; off; off >>= 1) s += __shfl_xor_sync(0xffffffffu, s, off);
        if (lane == 0) proj[p] = s;
    }
    __syncthreads();
    float m = -1e30f, se = 0.f;
    for (int w = tid; w < nw; w += 128) {
        const float* wr = W + (size_t)w * d;
        float l = 0.f;
        for (int k = 0; k < d; k++) l = fmaf(proj[k], wr[k], l);
        if (w == tgt - lo) s_tl = l;
        if (l > m) { se = se * __expf(m - l) + 1.f; m = l; }
        else       se += __expf(l - m);
    }
    rm[tid] = m; rs[tid] = se;
    __syncthreads();
    if (tid == 0) {
        float M = -1e30f;
        for (int i = 0; i < 128; i++) M = fmaxf(M, rm[i]);
        float S = 0.f;
        for (int i = 0; i < 128; i++) S += rs[i] * __expf(rm[i] - M);
        g_ct[r] = (M + logf(S)) - s_tl;
    }
}

// ---------- assemble + deterministic sum ----------
__global__ void k_final(const int* __restrict__ target) {
    int r = blockIdx.x * blockDim.x + threadIdx.x;
    if (r >= NROWS) return;
    int tgt = target[r];
    int rr = g_rev[r >> 8] * 256 + (r & 255);
    float nll;
    if (tgt == 0) nll = 0.f;
    else if (tgt < 30) nll = g_hl[r] - g_logits[(size_t)rr * 64 + tgt];
    else {
        int ci = tgt < 100 ? 0 : (tgt < 1000 ? 1 : 2);
        nll = (g_hl[r] - g_logits[(size_t)rr * 64 + 30 + ci]) + g_ct[r];
    }
    g_nll[r] = nll;
}

__global__ void k_sum(float* __restrict__ out) {
    __shared__ float sd[256];
    int tid = threadIdx.x;
    float s = 0.f;
    for (int i = tid; i < NROWS; i += 256) s += g_nll[i];
    sd[tid] = s;
    __syncthreads();
    for (int st = 128; st; st >>= 1) {
        if (tid < st) sd[tid] += sd[tid + st];
        __syncthreads();
    }
    if (tid == 0) out[0] = sd[0];
}

#define RNN_SMEM ((24 * HH + 2 * 32 * 257) * 4)

extern "C" void kernel_launch(void* const* d_in, const int* in_sizes, int n_in,
                              void* d_out, int out_size) {
    const float* z      = (const float*)d_in[0];
    const float* emb    = (const float*)d_in[1];
    const float* l2h_w  = (const float*)d_in[2];
    const float* l2h_b  = (const float*)d_in[3];
    const float* r0wih  = (const float*)d_in[4];
    const float* r0whh  = (const float*)d_in[5];
    const float* r0bih  = (const float*)d_in[6];
    const float* r0bhh  = (const float*)d_in[7];
    const float* r1wih  = (const float*)d_in[8];
    const float* r1whh  = (const float*)d_in[9];
    const float* r1bih  = (const float*)d_in[10];
    const float* r1bhh  = (const float*)d_in[11];
    const float* head_w = (const float*)d_in[12];
    const float* tp0    = (const float*)d_in[13];
    const float* tw0    = (const float*)d_in[14];
    const float* tp1    = (const float*)d_in[15];
    const float* tw1    = (const float*)d_in[16];
    const float* tp2    = (const float*)d_in[17];
    const float* tw2    = (const float*)d_in[18];
    const int*   inp    = (const int*)d_in[19];
    const int*   target = (const int*)d_in[20];
    const int*   length = (const int*)d_in[21];
    float* out = (float*)d_out;

    float* gh1 = nullptr; float* gh2 = nullptr; float* gz = nullptr; float* gpw = nullptr;
    float* ghid = nullptr; float* gpre = nullptr; float* glog = nullptr;
    cudaGetSymbolAddress((void**)&gh1, g_h1);
    cudaGetSymbolAddress((void**)&gh2, g_h2);
    cudaGetSymbolAddress((void**)&gz, g_zero);
    cudaGetSymbolAddress((void**)&gpw, g_pw);
    cudaGetSymbolAddress((void**)&ghid, g_hidden);
    cudaGetSymbolAddress((void**)&gpre, g_pre);
    cudaGetSymbolAddress((void**)&glog, g_logits);

    cudaFuncSetAttribute(k_rnn_fused, cudaFuncAttributeMaxDynamicSharedMemorySize, RNN_SMEM);

    k_prep<<<1, 32>>>(length);
    k_tok<<<NROWS / 256, 256>>>(inp);
    k_hidden<<<(2 * BB * HH) / 256, 256>>>(z, l2h_w, l2h_b);
    k_pack<<<64 * HH / 256, 256>>>(head_w, tp2);

    // layer 0 input pre-activations: emb[tok] @ W0ih^T + b0ih + b0hh
    k_sgemm<<<dim3(64, 16), 256>>>(emb, r0wih, r0bih, r0bhh, gpre, 512, HH, 1);
    // fused 2-layer recurrence (L1 input matvec folded in)
    k_rnn_fused<<<NBLK, 256, RNN_SMEM>>>(r0whh, r1wih, r1whh, gpre,
                                         r1bih, r1bhh, ghid, gh1, gh2);

    // packed head + tail2-proj logits: [8192 x 64]
    k_sgemm<<<dim3(64, 1), 256>>>(gh2, gpw, gz, gz, glog, HH, 64, 0);

    k_head<<<NROWS / 256, 256>>>();
    k_tail2<<<NROWS / 32, 128>>>(tw2, target);
    k_tail01<<<NROWS, 128>>>(tp0, tw0, tp1, tw1, target);
    k_final<<<NROWS / 256, 256>>>(target);
    k_sum<<<1, 256>>>(out);
    (void)in_sizes; (void)n_in; (void)out_size;
}

// round 9
// speedup vs baseline: 2.3766x; 1.1026x over previous
#include <cuda_runtime.h>
#include <math.h>

#define BB    32
#define SS    256
#define HH    1024
#define NROWS 8192
#define NBLK  128

typedef unsigned long long ull;

__device__ int    g_sorted[BB];
__device__ int    g_rev[BB];
__device__ int    g_tok[NROWS];
__device__ float  g_hidden[2 * BB * HH];
__device__ float  g_pre[NROWS * HH];
__device__ float  g_h1[(size_t)NROWS * HH];
__device__ float  g_h2[(size_t)NROWS * HH];
__device__ float  g_pw[64 * HH];          // packed: head_w rows 0..32, tp2 rows 36..51
__device__ float  g_logits[NROWS * 64];
__device__ float  g_hl[NROWS];
__device__ float  g_ct[NROWS];
__device__ float  g_nll[NROWS];
__device__ float  g_zero[64];
__device__ unsigned g_cnt;

// packed fp32x2 FMA: d = a*b + d  (per-lane IEEE fp32)
__device__ __forceinline__ void ffma2(ull& d, ull a, ull b) {
    asm("fma.rn.f32x2 %0, %1, %2, %0;" : "+l"(d) : "l"(a), "l"(b));
}
__device__ __forceinline__ ull packdup(float x) {
    ull r;
    asm("mov.b64 %0, {%1, %1};" : "=l"(r) : "r"(__float_as_uint(x)));
    return r;
}
__device__ __forceinline__ float pairsum(ull v) {
    float2 f = *reinterpret_cast<float2*>(&v);
    return f.x + f.y;
}

// ---------- prep ----------
__global__ void k_prep(const int* __restrict__ len) {
    if (threadIdx.x == 0) {
        g_cnt = 0;
        int idx[BB];
        for (int i = 0; i < BB; i++) idx[i] = i;
        for (int i = 1; i < BB; i++) {               // stable desc insertion sort
            int v = idx[i], lv = len[v], j = i - 1;
            while (j >= 0 && len[idx[j]] < lv) { idx[j + 1] = idx[j]; j--; }
            idx[j + 1] = v;
        }
        for (int p = 0; p < BB; p++) { g_sorted[p] = idx[p]; g_rev[idx[p]] = p; }
    }
}

__global__ void k_tok(const int* __restrict__ inp) {
    int r = blockIdx.x * blockDim.x + threadIdx.x;
    if (r < NROWS) g_tok[r] = inp[g_sorted[r >> 8] * SS + (r & 255)];
}

// hid = z @ l2h_w^T + b   (flat view == .view(2,B,H))
__global__ void k_hidden(const float* __restrict__ z, const float* __restrict__ w,
                         const float* __restrict__ b) {
    int o = blockIdx.x * blockDim.x + threadIdx.x;
    if (o >= 2 * BB * HH) return;
    const float* zr = z + (o >> 11) * 256;
    const float* wr = w + (size_t)(o & 2047) * 256;
    float acc = 0.f;
#pragma unroll 8
    for (int k = 0; k < 256; k++) acc = fmaf(zr[k], wr[k], acc);
    g_hidden[o] = acc + b[o & 2047];
}

__global__ void k_pack(const float* __restrict__ head_w, const float* __restrict__ tp2) {
    int i = blockIdx.x * blockDim.x + threadIdx.x;
    if (i >= 64 * HH) return;
    int row = i >> 10, c = i & 1023;
    float v = 0.f;
    if (row < 33)                 v = head_w[row * HH + c];
    else if (row >= 36 && row < 52) v = tp2[(row - 36) * HH + c];
    g_pw[i] = v;
}

// ---------- SGEMM (f32x2): C[n][m] = A[row(n)][:K] . Bw[m][:K] + b1[m]+b2[m] ----------
__global__ void __launch_bounds__(256)
k_sgemm(const float* __restrict__ A, const float* __restrict__ Bw,
        const float* __restrict__ b1, const float* __restrict__ b2,
        float* __restrict__ C, int K, int M, int gather) {
    __shared__ __align__(16) float As[16][128];
    __shared__ __align__(16) float Bs[16][64];
    int tid = threadIdx.x, tx = tid & 15, ty = tid >> 4;
    int n0 = blockIdx.x * 128, m0 = blockIdx.y * 64;
    ull acc2[8][2];
#pragma unroll
    for (int r = 0; r < 8; r++) { acc2[r][0] = 0ull; acc2[r][1] = 0ull; }

    for (int k0 = 0; k0 < K; k0 += 16) {
#pragma unroll
        for (int i = 0; i < 2; i++) {
            int id = tid * 2 + i, r = id >> 2, kq = (id & 3) * 4;
            int grow = n0 + r;
            int arow = gather ? g_tok[grow] : grow;
            float4 v = *(const float4*)(A + (size_t)arow * K + k0 + kq);
            As[kq][r] = v.x; As[kq + 1][r] = v.y; As[kq + 2][r] = v.z; As[kq + 3][r] = v.w;
        }
        {
            int m = tid >> 2, kq = (tid & 3) * 4;
            float4 v = *(const float4*)(Bw + (size_t)(m0 + m) * K + k0 + kq);
            Bs[kq][m] = v.x; Bs[kq + 1][m] = v.y; Bs[kq + 2][m] = v.z; Bs[kq + 3][m] = v.w;
        }
        __syncthreads();
#pragma unroll
        for (int k = 0; k < 16; k++) {
            float4 a0 = *(float4*)&As[k][ty * 8];
            float4 a1 = *(float4*)&As[k][ty * 8 + 4];
            const ull* bp = (const ull*)&Bs[k][tx * 4];
            ull b01 = bp[0], b23 = bp[1];
            float a[8] = {a0.x, a0.y, a0.z, a0.w, a1.x, a1.y, a1.z, a1.w};
#pragma unroll
            for (int r = 0; r < 8; r++) {
                ull ap = packdup(a[r]);
                ffma2(acc2[r][0], ap, b01);
                ffma2(acc2[r][1], ap, b23);
            }
        }
        __syncthreads();
    }
    float bias[4];
#pragma unroll
    for (int c = 0; c < 4; c++) { int m = m0 + tx * 4 + c; bias[c] = b1[m] + b2[m]; }
#pragma unroll
    for (int r = 0; r < 8; r++) {
        int n = n0 + ty * 8 + r;
        float2 p0 = *(float2*)&acc2[r][0];
        float2 p1 = *(float2*)&acc2[r][1];
        float4 v = make_float4(p0.x + bias[0], p0.y + bias[1],
                               p1.x + bias[2], p1.y + bias[3]);
        *(float4*)(C + (size_t)n * M + m0 + tx * 4) = v;
    }
}

// ---------- grid barrier: REDG arrive + direct counter poll (monotonic epochs) ----------
__device__ __forceinline__ void gridbar_ep(unsigned ep) {
    __syncthreads();
    if (threadIdx.x == 0) {
        __threadfence();
        asm volatile("red.release.gpu.global.add.u32 [%0], 1;"
                     :: "l"(&g_cnt) : "memory");
        unsigned tgtv = ep * (unsigned)NBLK;
        unsigned v;
        do {
            asm volatile("ld.acquire.gpu.global.u32 %0, [%1];"
                         : "=r"(v) : "l"(&g_cnt) : "memory");
        } while (v < tgtv);
    }
    __syncthreads();
}

// ---------- fused 2-layer persistent RNN ----------
// 128 CTAs x 256 thr; CTA owns j0..j0+7 of BOTH layers. Uniform steps:
// combined pass loads h1(s-1) ONCE and feeds both W0hh (-> h1(s)) and
// W1ih (-> h2(s-1) input); W1hh pass accumulates into the same registers.
// Edge steps computed uniformly, stores guarded. ONE barrier/step (257).
__global__ void __launch_bounds__(256, 1)
k_rnn_fused(const float* __restrict__ W0hh, const float* __restrict__ W1ih,
            const float* __restrict__ W1hh, const float* __restrict__ pre1,
            const float* __restrict__ b1ih, const float* __restrict__ b1hh,
            const float* __restrict__ hid,
            float* __restrict__ h1seq, float* __restrict__ h2seq) {
    extern __shared__ float sm[];
    float* Ws0 = sm;                 // [8][1024]
    float* Wsi = sm + 8 * HH;
    float* Wsh = sm + 16 * HH;
    float* Part0 = sm + 24 * HH;     // [32][257]
    float* Part1 = Part0 + 32 * 257;
    int tid = threadIdx.x, bid = blockIdx.x;
    int w = tid >> 5, lane = tid & 31;
    int j0 = bid * 8;

    {   // load 3 W slices, coalesced float4
        const float4* s0 = (const float4*)(W0hh + (size_t)j0 * HH);
        const float4* s1 = (const float4*)(W1ih + (size_t)j0 * HH);
        const float4* s2 = (const float4*)(W1hh + (size_t)j0 * HH);
        float4* d0 = (float4*)Ws0; float4* d1 = (float4*)Wsi; float4* d2 = (float4*)Wsh;
        for (int i = tid; i < 8 * 256; i += 256) { d0[i] = s0[i]; d1[i] = s1[i]; d2[i] = s2[i]; }
    }
    __syncthreads();

    int b0 = w * 4;              // warp's 4 batch rows
    int kl = lane * 4;           // lane's k offset
    int b2 = tid >> 3, jj2 = tid & 7;   // reduce-phase output (b, j)
    float bias1v = b1ih[j0 + jj2] + b1hh[j0 + jj2];
    const float* pre_base = pre1 + ((size_t)b2 * SS) * HH + j0 + jj2;
    float* out1 = h1seq + ((size_t)b2 * SS) * HH + j0 + jj2;
    float* out2 = h2seq + ((size_t)b2 * SS) * HH + j0 + jj2;
    const float* hid0 = hid;
    const float* hid1 = hid + BB * HH;

    for (int s = 0; s <= SS; s++) {
        float pre_v = (s < SS) ? __ldcg(&pre_base[(size_t)s * HH]) : 0.f;

        const float* p[4];       // h1(s-1) (or hid0 at s=0)
        const float* r[4];       // h2(s-2) (or hid1 at s<=1)
#pragma unroll
        for (int bl = 0; bl < 4; bl++) {
            p[bl] = (s == 0) ? (hid0 + (b0 + bl) * HH + kl)
                             : (h1seq + ((size_t)(b0 + bl) * SS + s - 1) * HH + kl);
            r[bl] = (s <= 1) ? (hid1 + (b0 + bl) * HH + kl)
                             : (h2seq + ((size_t)(b0 + bl) * SS + s - 2) * HH + kl);
        }

        ull acc0[4][8], accI[4][8];
#pragma unroll
        for (int bl = 0; bl < 4; bl++)
#pragma unroll
            for (int j = 0; j < 8; j++) { acc0[bl][j] = 0ull; accI[bl][j] = 0ull; }

        // combined pass: h1 shared by W0hh and W1ih
#pragma unroll
        for (int q = 0; q < 8; q++) {
            ulonglong2 hq[4];
#pragma unroll
            for (int bl = 0; bl < 4; bl++)
                hq[bl] = __ldcg((const ulonglong2*)(p[bl] + q * 128));
#pragma unroll
            for (int j = 0; j < 8; j++) {
                ulonglong2 w0 = *(const ulonglong2*)(Ws0 + j * HH + q * 128 + kl);
                ulonglong2 wi = *(const ulonglong2*)(Wsi + j * HH + q * 128 + kl);
#pragma unroll
                for (int bl = 0; bl < 4; bl++) {
                    ffma2(acc0[bl][j], hq[bl].x, w0.x);
                    ffma2(acc0[bl][j], hq[bl].y, w0.y);
                    ffma2(accI[bl][j], hq[bl].x, wi.x);
                    ffma2(accI[bl][j], hq[bl].y, wi.y);
                }
            }
        }
        // W1hh pass: h2(s-2), accumulate into accI
#pragma unroll
        for (int q = 0; q < 8; q++) {
            ulonglong2 hq[4];
#pragma unroll
            for (int bl = 0; bl < 4; bl++)
                hq[bl] = __ldcg((const ulonglong2*)(r[bl] + q * 128));
#pragma unroll
            for (int j = 0; j < 8; j++) {
                ulonglong2 wh = *(const ulonglong2*)(Wsh + j * HH + q * 128 + kl);
#pragma unroll
                for (int bl = 0; bl < 4; bl++) {
                    ffma2(accI[bl][j], hq[bl].x, wh.x);
                    ffma2(accI[bl][j], hq[bl].y, wh.y);
                }
            }
        }
        // write partials (stride 257 -> conflict-free)
#pragma unroll
        for (int bl = 0; bl < 4; bl++)
#pragma unroll
            for (int j = 0; j < 8; j++) {
                Part0[lane * 257 + w * 32 + bl * 8 + j] = pairsum(acc0[bl][j]);
                Part1[lane * 257 + w * 32 + bl * 8 + j] = pairsum(accI[bl][j]);
            }
        __syncthreads();

        if (s < SS) {
            float sum = pre_v;
#pragma unroll
            for (int l = 0; l < 32; l++) sum += Part0[l * 257 + tid];
            __stcg(&out1[(size_t)s * HH], tanhf(sum));
        }
        if (s >= 1) {
            float sum = bias1v;
#pragma unroll
            for (int l = 0; l < 32; l++) sum += Part1[l * 257 + tid];
            __stcg(&out2[(size_t)(s - 1) * HH], tanhf(sum));
        }
        gridbar_ep((unsigned)(s + 1));
    }
}

// ---------- head logsumexp (33 logits) ----------
__global__ void k_head() {
    int r = blockIdx.x * blockDim.x + threadIdx.x;
    if (r >= NROWS) return;
    int rr = g_rev[r >> 8] * 256 + (r & 255);
    const float* L = g_logits + (size_t)rr * 64;
    float m = -1e30f;
    for (int j = 0; j < 33; j++) m = fmaxf(m, L[j]);
    float se = 0.f;
    for (int j = 0; j < 33; j++) se += __expf(L[j] - m);
    g_hl[r] = m + logf(se);
}

// ---------- tail cluster 2 (19000 words x 16): warp=word-stripe, lane=row ----------
__global__ void __launch_bounds__(128)
k_tail2(const float* __restrict__ tw2, const int* __restrict__ target) {
    __shared__ float s_tl[32], s_m[4][32], s_s[4][32];
    int tid = threadIdx.x, warp = tid >> 5, lane = tid & 31;
    int r = blockIdx.x * 32 + lane;
    int tgt = target[r];
    int rr = g_rev[r >> 8] * 256 + (r & 255);
    const ulonglong2* pr = (const ulonglong2*)&g_logits[(size_t)rr * 64 + 36];
    ulonglong2 p0 = pr[0], p1 = pr[1], p2 = pr[2], p3 = pr[3];
    int wt = tgt - 1000;
    float m = -1e30f, se = 0.f;
    for (int w = warp; w < 19000; w += 4) {
        const ulonglong2* wr = (const ulonglong2*)(tw2 + (size_t)w * 16);
        ulonglong2 q0 = wr[0], q1 = wr[1], q2 = wr[2], q3 = wr[3];
        ull a = 0ull;
        ffma2(a, p0.x, q0.x); ffma2(a, p0.y, q0.y);
        ffma2(a, p1.x, q1.x); ffma2(a, p1.y, q1.y);
        ffma2(a, p2.x, q2.x); ffma2(a, p2.y, q2.y);
        ffma2(a, p3.x, q3.x); ffma2(a, p3.y, q3.y);
        float l = pairsum(a);
        if (w == wt) s_tl[lane] = l;
        if (l > m) { se = se * __expf(m - l) + 1.f; m = l; }
        else       se += __expf(l - m);
    }
    s_m[warp][lane] = m; s_s[warp][lane] = se;
    __syncthreads();
    if (warp == 0) {
        float M = s_m[0][lane];
        for (int q = 1; q < 4; q++) M = fmaxf(M, s_m[q][lane]);
        float S = 0.f;
        for (int q = 0; q < 4; q++) S += s_s[q][lane] * __expf(s_m[q][lane] - M);
        if (tgt >= 1000) g_ct[r] = (M + logf(S)) - s_tl[lane];
    }
}

// ---------- tail clusters 0/1 (rare rows), early exit ----------
__global__ void __launch_bounds__(128)
k_tail01(const float* __restrict__ tp0, const float* __restrict__ tw0,
         const float* __restrict__ tp1, const float* __restrict__ tw1,
         const int* __restrict__ target) {
    int r = blockIdx.x;
    int tgt = target[r];
    if (tgt < 30 || tgt >= 1000) return;
    int lo, nw, d; const float *P, *W;
    if (tgt < 100) { lo = 30; nw = 70; d = 256; P = tp0; W = tw0; }
    else           { lo = 100; nw = 900; d = 64; P = tp1; W = tw1; }
    int tid = threadIdx.x, lane = tid & 31, warp = tid >> 5;
    int rr = g_rev[r >> 8] * 256 + (r & 255);
    __shared__ float xs[HH], proj[256], rm[128], rs[128], s_tl;
    const float* xr = g_h2 + (size_t)rr * HH;
    for (int i = tid; i < HH; i += 128) xs[i] = xr[i];
    __syncthreads();
    for (int p = warp; p < d; p += 4) {
        const float* wr = P + (size_t)p * HH;
        float s = 0.f;
        for (int k = lane; k < HH; k += 32) s = fmaf(xs[k], wr[k], s);
#pragma unroll
        for (int off = 16; off; off >>= 1) s += __shfl_xor_sync(0xffffffffu, s, off);
        if (lane == 0) proj[p] = s;
    }
    __syncthreads();
    float m = -1e30f, se = 0.f;
    for (int w = tid; w < nw; w += 128) {
        const float* wr = W + (size_t)w * d;
        float l = 0.f;
        for (int k = 0; k < d; k++) l = fmaf(proj[k], wr[k], l);
        if (w == tgt - lo) s_tl = l;
        if (l > m) { se = se * __expf(m - l) + 1.f; m = l; }
        else       se += __expf(l - m);
    }
    rm[tid] = m; rs[tid] = se;
    __syncthreads();
    if (tid == 0) {
        float M = -1e30f;
        for (int i = 0; i < 128; i++) M = fmaxf(M, rm[i]);
        float S = 0.f;
        for (int i = 0; i < 128; i++) S += rs[i] * __expf(rm[i] - M);
        g_ct[r] = (M + logf(S)) - s_tl;
    }
}

// ---------- assemble + deterministic sum ----------
__global__ void k_final(const int* __restrict__ target) {
    int r = blockIdx.x * blockDim.x + threadIdx.x;
    if (r >= NROWS) return;
    int tgt = target[r];
    int rr = g_rev[r >> 8] * 256 + (r & 255);
    float nll;
    if (tgt == 0) nll = 0.f;
    else if (tgt < 30) nll = g_hl[r] - g_logits[(size_t)rr * 64 + tgt];
    else {
        int ci = tgt < 100 ? 0 : (tgt < 1000 ? 1 : 2);
        nll = (g_hl[r] - g_logits[(size_t)rr * 64 + 30 + ci]) + g_ct[r];
    }
    g_nll[r] = nll;
}

__global__ void k_sum(float* __restrict__ out) {
    __shared__ float sd[256];
    int tid = threadIdx.x;
    float s = 0.f;
    for (int i = tid; i < NROWS; i += 256) s += g_nll[i];
    sd[tid] = s;
    __syncthreads();
    for (int st = 128; st; st >>= 1) {
        if (tid < st) sd[tid] += sd[tid + st];
        __syncthreads();
    }
    if (tid == 0) out[0] = sd[0];
}

#define RNN_SMEM ((24 * HH + 2 * 32 * 257) * 4)

extern "C" void kernel_launch(void* const* d_in, const int* in_sizes, int n_in,
                              void* d_out, int out_size) {
    const float* z      = (const float*)d_in[0];
    const float* emb    = (const float*)d_in[1];
    const float* l2h_w  = (const float*)d_in[2];
    const float* l2h_b  = (const float*)d_in[3];
    const float* r0wih  = (const float*)d_in[4];
    const float* r0whh  = (const float*)d_in[5];
    const float* r0bih  = (const float*)d_in[6];
    const float* r0bhh  = (const float*)d_in[7];
    const float* r1wih  = (const float*)d_in[8];
    const float* r1whh  = (const float*)d_in[9];
    const float* r1bih  = (const float*)d_in[10];
    const float* r1bhh  = (const float*)d_in[11];
    const float* head_w = (const float*)d_in[12];
    const float* tp0    = (const float*)d_in[13];
    const float* tw0    = (const float*)d_in[14];
    const float* tp1    = (const float*)d_in[15];
    const float* tw1    = (const float*)d_in[16];
    const float* tp2    = (const float*)d_in[17];
    const float* tw2    = (const float*)d_in[18];
    const int*   inp    = (const int*)d_in[19];
    const int*   target = (const int*)d_in[20];
    const int*   length = (const int*)d_in[21];
    float* out = (float*)d_out;

    float* gh1 = nullptr; float* gh2 = nullptr; float* gz = nullptr; float* gpw = nullptr;
    float* ghid = nullptr; float* gpre = nullptr; float* glog = nullptr;
    cudaGetSymbolAddress((void**)&gh1, g_h1);
    cudaGetSymbolAddress((void**)&gh2, g_h2);
    cudaGetSymbolAddress((void**)&gz, g_zero);
    cudaGetSymbolAddress((void**)&gpw, g_pw);
    cudaGetSymbolAddress((void**)&ghid, g_hidden);
    cudaGetSymbolAddress((void**)&gpre, g_pre);
    cudaGetSymbolAddress((void**)&glog, g_logits);

    cudaFuncSetAttribute(k_rnn_fused, cudaFuncAttributeMaxDynamicSharedMemorySize, RNN_SMEM);

    k_prep<<<1, 32>>>(length);
    k_tok<<<NROWS / 256, 256>>>(inp);
    k_hidden<<<(2 * BB * HH) / 256, 256>>>(z, l2h_w, l2h_b);
    k_pack<<<64 * HH / 256, 256>>>(head_w, tp2);

    // layer 0 input pre-activations: emb[tok] @ W0ih^T + b0ih + b0hh
    k_sgemm<<<dim3(64, 16), 256>>>(emb, r0wih, r0bih, r0bhh, gpre, 512, HH, 1);
    // fused 2-layer recurrence (L1 input matvec folded in, shared h1 loads)
    k_rnn_fused<<<NBLK, 256, RNN_SMEM>>>(r0whh, r1wih, r1whh, gpre,
                                         r1bih, r1bhh, ghid, gh1, gh2);

    // packed head + tail2-proj logits: [8192 x 64]
    k_sgemm<<<dim3(64, 1), 256>>>(gh2, gpw, gz, gz, glog, HH, 64, 0);

    k_head<<<NROWS / 256, 256>>>();
    k_tail2<<<NROWS / 32, 128>>>(tw2, target);
    k_tail01<<<NROWS, 128>>>(tp0, tw0, tp1, tw1, target);
    k_final<<<NROWS / 256, 256>>>(target);
    k_sum<<<1, 256>>>(out);
    (void)in_sizes; (void)n_in; (void)out_size;
}

// round 11
// speedup vs baseline: 2.4137x; 1.0156x over previous
#include <cuda_runtime.h>
#include <cuda_bf16.h>
#include <math.h>

#define BB    32
#define SS    256
#define HH    1024
#define NROWS 8192
#define NBLK  128

typedef unsigned long long ull;

__device__ int    g_sorted[BB];
__device__ int    g_rev[BB];
__device__ int    g_tok[NROWS];
__device__ __nv_bfloat16 g_hiddenb[2 * BB * HH];
__device__ float  g_pre[NROWS * HH];
__device__ __nv_bfloat16 g_h1b[(size_t)NROWS * HH];
__device__ __nv_bfloat16 g_h2b[(size_t)NROWS * HH];
__device__ float  g_h2[(size_t)NROWS * HH];
__device__ float  g_pw[64 * HH];          // packed: head_w rows 0..32, tp2 rows 36..51
__device__ float  g_logits[NROWS * 64];
__device__ float  g_hl[NROWS];
__device__ float  g_ct[NROWS];
__device__ float  g_nll[NROWS];
__device__ float  g_zero[64];
__device__ unsigned g_cnt;

// packed fp32x2 FMA: d = a*b + d  (per-lane IEEE fp32)
__device__ __forceinline__ void ffma2(ull& d, ull a, ull b) {
    asm("fma.rn.f32x2 %0, %1, %2, %0;" : "+l"(d) : "l"(a), "l"(b));
}
__device__ __forceinline__ ull packdup(float x) {
    ull r;
    asm("mov.b64 %0, {%1, %1};" : "=l"(r) : "r"(__float_as_uint(x)));
    return r;
}
__device__ __forceinline__ float pairsum(ull v) {
    float2 f = *reinterpret_cast<float2*>(&v);
    return f.x + f.y;
}
// two packed bf16 -> f32x2 (bf16 to f32 is a 16-bit upshift)
__device__ __forceinline__ ull bf2_up(unsigned w) {
    ull r;
    asm("mov.b64 %0, {%1, %2};" : "=l"(r) : "r"(w << 16), "r"(w & 0xFFFF0000u));
    return r;
}

// ---------- prep: sort + token gather in ONE launch ----------
__global__ void k_preptok(const int* __restrict__ len, const int* __restrict__ inp) {
    __shared__ int s_sorted[BB];
    int tid = threadIdx.x;
    if (tid == 0) {
        g_cnt = 0;
        int idx[BB];
        for (int i = 0; i < BB; i++) idx[i] = i;
        for (int i = 1; i < BB; i++) {               // stable desc insertion sort
            int v = idx[i], lv = len[v], j = i - 1;
            while (j >= 0 && len[idx[j]] < lv) { idx[j + 1] = idx[j]; j--; }
            idx[j + 1] = v;
        }
        for (int p = 0; p < BB; p++) {
            g_sorted[p] = idx[p]; g_rev[idx[p]] = p; s_sorted[p] = idx[p];
        }
    }
    __syncthreads();
    for (int r = tid; r < NROWS; r += blockDim.x)
        g_tok[r] = inp[s_sorted[r >> 8] * SS + (r & 255)];
}

// hid = z @ l2h_w^T + b  (flat view == .view(2,B,H)), stored bf16 for the recurrence
__global__ void k_hidden(const float* __restrict__ z, const float* __restrict__ w,
                         const float* __restrict__ b) {
    int o = blockIdx.x * blockDim.x + threadIdx.x;
    if (o >= 2 * BB * HH) return;
    const float* zr = z + (o >> 11) * 256;
    const float* wr = w + (size_t)(o & 2047) * 256;
    float acc = 0.f;
#pragma unroll 8
    for (int k = 0; k < 256; k++) acc = fmaf(zr[k], wr[k], acc);
    g_hiddenb[o] = __float2bfloat16(acc + b[o & 2047]);
}

__global__ void k_pack(const float* __restrict__ head_w, const float* __restrict__ tp2) {
    int i = blockIdx.x * blockDim.x + threadIdx.x;
    if (i >= 64 * HH) return;
    int row = i >> 10, c = i & 1023;
    float v = 0.f;
    if (row < 33)                 v = head_w[row * HH + c];
    else if (row >= 36 && row < 52) v = tp2[(row - 36) * HH + c];
    g_pw[i] = v;
}

// ---------- SGEMM (f32x2): C[n][m] = A[row(n)][:K] . Bw[m][:K] + b1[m]+b2[m] ----------
__global__ void __launch_bounds__(256)
k_sgemm(const float* __restrict__ A, const float* __restrict__ Bw,
        const float* __restrict__ b1, const float* __restrict__ b2,
        float* __restrict__ C, int K, int M, int gather) {
    __shared__ __align__(16) float As[16][128];
    __shared__ __align__(16) float Bs[16][64];
    int tid = threadIdx.x, tx = tid & 15, ty = tid >> 4;
    int n0 = blockIdx.x * 128, m0 = blockIdx.y * 64;
    ull acc2[8][2];
#pragma unroll
    for (int r = 0; r < 8; r++) { acc2[r][0] = 0ull; acc2[r][1] = 0ull; }

    for (int k0 = 0; k0 < K; k0 += 16) {
#pragma unroll
        for (int i = 0; i < 2; i++) {
            int id = tid * 2 + i, r = id >> 2, kq = (id & 3) * 4;
            int grow = n0 + r;
            int arow = gather ? g_tok[grow] : grow;
            float4 v = *(const float4*)(A + (size_t)arow * K + k0 + kq);
            As[kq][r] = v.x; As[kq + 1][r] = v.y; As[kq + 2][r] = v.z; As[kq + 3][r] = v.w;
        }
        {
            int m = tid >> 2, kq = (tid & 3) * 4;
            float4 v = *(const float4*)(Bw + (size_t)(m0 + m) * K + k0 + kq);
            Bs[kq][m] = v.x; Bs[kq + 1][m] = v.y; Bs[kq + 2][m] = v.z; Bs[kq + 3][m] = v.w;
        }
        __syncthreads();
#pragma unroll
        for (int k = 0; k < 16; k++) {
            float4 a0 = *(float4*)&As[k][ty * 8];
            float4 a1 = *(float4*)&As[k][ty * 8 + 4];
            const ull* bp = (const ull*)&Bs[k][tx * 4];
            ull b01 = bp[0], b23 = bp[1];
            float a[8] = {a0.x, a0.y, a0.z, a0.w, a1.x, a1.y, a1.z, a1.w};
#pragma unroll
            for (int r = 0; r < 8; r++) {
                ull ap = packdup(a[r]);
                ffma2(acc2[r][0], ap, b01);
                ffma2(acc2[r][1], ap, b23);
            }
        }
        __syncthreads();
    }
    float bias[4];
#pragma unroll
    for (int c = 0; c < 4; c++) { int m = m0 + tx * 4 + c; bias[c] = b1[m] + b2[m]; }
#pragma unroll
    for (int r = 0; r < 8; r++) {
        int n = n0 + ty * 8 + r;
        float2 p0 = *(float2*)&acc2[r][0];
        float2 p1 = *(float2*)&acc2[r][1];
        float4 v = make_float4(p0.x + bias[0], p0.y + bias[1],
                               p1.x + bias[2], p1.y + bias[3]);
        *(float4*)(C + (size_t)n * M + m0 + tx * 4) = v;
    }
}

// ---------- grid barrier: REDG arrive + direct counter poll (monotonic epochs) ----------
__device__ __forceinline__ void gridbar_ep(unsigned ep) {
    __syncthreads();
    if (threadIdx.x == 0) {
        __threadfence();
        asm volatile("red.release.gpu.global.add.u32 [%0], 1;"
                     :: "l"(&g_cnt) : "memory");
        unsigned tgtv = ep * (unsigned)NBLK;
        unsigned v;
        do {
            asm volatile("ld.acquire.gpu.global.u32 %0, [%1];"
                         : "=r"(v) : "l"(&g_cnt) : "memory");
        } while (v < tgtv);
    }
    __syncthreads();
}

// ---------- fused 2-layer persistent RNN, bf16 hidden-state storage ----------
// 128 CTAs x 256 thr; CTA owns j0..j0+7 of BOTH layers. h1/h2 recurrence state
// stored bf16 (halves L2 broadcast); converted to f32x2 via 16-bit upshift.
// h2 also written fp32 for downstream softmax. ONE barrier/step (257).
__global__ void __launch_bounds__(256, 1)
k_rnn_fused(const float* __restrict__ W0hh, const float* __restrict__ W1ih,
            const float* __restrict__ W1hh, const float* __restrict__ pre1,
            const float* __restrict__ b1ih, const float* __restrict__ b1hh,
            const __nv_bfloat16* __restrict__ hidb,
            __nv_bfloat16* __restrict__ h1b,
            float* __restrict__ h2f, __nv_bfloat16* __restrict__ h2b) {
    extern __shared__ float sm[];
    float* Ws0 = sm;                 // [8][1024]
    float* Wsi = sm + 8 * HH;
    float* Wsh = sm + 16 * HH;
    float* Part0 = sm + 24 * HH;     // [32][257]
    float* Part1 = Part0 + 32 * 257;
    int tid = threadIdx.x, bid = blockIdx.x;
    int w = tid >> 5, lane = tid & 31;
    int j0 = bid * 8;

    {   // load 3 W slices, coalesced float4
        const float4* s0 = (const float4*)(W0hh + (size_t)j0 * HH);
        const float4* s1 = (const float4*)(W1ih + (size_t)j0 * HH);
        const float4* s2 = (const float4*)(W1hh + (size_t)j0 * HH);
        float4* d0 = (float4*)Ws0; float4* d1 = (float4*)Wsi; float4* d2 = (float4*)Wsh;
        for (int i = tid; i < 8 * 256; i += 256) { d0[i] = s0[i]; d1[i] = s1[i]; d2[i] = s2[i]; }
    }
    __syncthreads();

    int b0 = w * 4;              // warp's 4 batch rows
    int kl = lane * 4;           // lane's k offset (4 elems = 8B bf16, coalesced)
    int b2 = tid >> 3, jj2 = tid & 7;   // reduce-phase output (b, j)
    float bias1v = b1ih[j0 + jj2] + b1hh[j0 + jj2];
    const float* pre_base = pre1 + ((size_t)b2 * SS) * HH + j0 + jj2;
    __nv_bfloat16* out1b = h1b + ((size_t)b2 * SS) * HH + j0 + jj2;
    float*         out2f = h2f + ((size_t)b2 * SS) * HH + j0 + jj2;
    __nv_bfloat16* out2b = h2b + ((size_t)b2 * SS) * HH + j0 + jj2;
    const __nv_bfloat16* hid0 = hidb;
    const __nv_bfloat16* hid1 = hidb + BB * HH;

    for (int s = 0; s <= SS; s++) {
        float pre_v = (s < SS) ? __ldcg(&pre_base[(size_t)s * HH]) : 0.f;

        const __nv_bfloat16* p[4];   // h1(s-1) (or hid0 at s=0)
        const __nv_bfloat16* r[4];   // h2(s-2) (or hid1 at s<=1)
#pragma unroll
        for (int bl = 0; bl < 4; bl++) {
            p[bl] = (s == 0) ? (hid0 + (b0 + bl) * HH + kl)
                             : (h1b + ((size_t)(b0 + bl) * SS + s - 1) * HH + kl);
            r[bl] = (s <= 1) ? (hid1 + (b0 + bl) * HH + kl)
                             : (h2b + ((size_t)(b0 + bl) * SS + s - 2) * HH + kl);
        }

        ull acc0[4][8], accI[4][8];
#pragma unroll
        for (int bl = 0; bl < 4; bl++)
#pragma unroll
            for (int j = 0; j < 8; j++) { acc0[bl][j] = 0ull; accI[bl][j] = 0ull; }

        // combined pass: h1 shared by W0hh and W1ih
#pragma unroll
        for (int q = 0; q < 8; q++) {
            ull hx[4], hy[4];
#pragma unroll
            for (int bl = 0; bl < 4; bl++) {
                uint2 hv = __ldcg((const uint2*)(p[bl] + q * 128));
                hx[bl] = bf2_up(hv.x);
                hy[bl] = bf2_up(hv.y);
            }
#pragma unroll
            for (int j = 0; j < 8; j++) {
                ulonglong2 w0 = *(const ulonglong2*)(Ws0 + j * HH + q * 128 + kl);
                ulonglong2 wi = *(const ulonglong2*)(Wsi + j * HH + q * 128 + kl);
#pragma unroll
                for (int bl = 0; bl < 4; bl++) {
                    ffma2(acc0[bl][j], hx[bl], w0.x);
                    ffma2(acc0[bl][j], hy[bl], w0.y);
                    ffma2(accI[bl][j], hx[bl], wi.x);
                    ffma2(accI[bl][j], hy[bl], wi.y);
                }
            }
        }
        // W1hh pass: h2(s-2), accumulate into accI
#pragma unroll
        for (int q = 0; q < 8; q++) {
            ull hx[4], hy[4];
#pragma unroll
            for (int bl = 0; bl < 4; bl++) {
                uint2 hv = __ldcg((const uint2*)(r[bl] + q * 128));
                hx[bl] = bf2_up(hv.x);
                hy[bl] = bf2_up(hv.y);
            }
#pragma unroll
            for (int j = 0; j < 8; j++) {
                ulonglong2 wh = *(const ulonglong2*)(Wsh + j * HH + q * 128 + kl);
#pragma unroll
                for (int bl = 0; bl < 4; bl++) {
                    ffma2(accI[bl][j], hx[bl], wh.x);
                    ffma2(accI[bl][j], hy[bl], wh.y);
                }
            }
        }
        // write partials (stride 257 -> conflict-free)
#pragma unroll
        for (int bl = 0; bl < 4; bl++)
#pragma unroll
            for (int j = 0; j < 8; j++) {
                Part0[lane * 257 + w * 32 + bl * 8 + j] = pairsum(acc0[bl][j]);
                Part1[lane * 257 + w * 32 + bl * 8 + j] = pairsum(accI[bl][j]);
            }
        __syncthreads();

        if (s < SS) {
            float sum = pre_v;
#pragma unroll
            for (int l = 0; l < 32; l++) sum += Part0[l * 257 + tid];
            out1b[(size_t)s * HH] = __float2bfloat16(tanhf(sum));
        }
        if (s >= 1) {
            float sum = bias1v;
#pragma unroll
            for (int l = 0; l < 32; l++) sum += Part1[l * 257 + tid];
            float hv = tanhf(sum);
            __stcg(&out2f[(size_t)(s - 1) * HH], hv);
            out2b[(size_t)(s - 1) * HH] = __float2bfloat16(hv);
        }
        gridbar_ep((unsigned)(s + 1));
    }
}

// ---------- head logsumexp (33 logits) ----------
__global__ void k_head() {
    int r = blockIdx.x * blockDim.x + threadIdx.x;
    if (r >= NROWS) return;
    int rr = g_rev[r >> 8] * 256 + (r & 255);
    const float* L = g_logits + (size_t)rr * 64;
    float m = -1e30f;
    for (int j = 0; j < 33; j++) m = fmaxf(m, L[j]);
    float se = 0.f;
    for (int j = 0; j < 33; j++) se += __expf(L[j] - m);
    g_hl[r] = m + logf(se);
}

// ---------- tail cluster 2 (19000 words x 16): warp=word-stripe, lane=row ----------
__global__ void __launch_bounds__(128)
k_tail2(const float* __restrict__ tw2, const int* __restrict__ target) {
    __shared__ float s_tl[32], s_m[4][32], s_s[4][32];
    int tid = threadIdx.x, warp = tid >> 5, lane = tid & 31;
    int r = blockIdx.x * 32 + lane;
    int tgt = target[r];
    int rr = g_rev[r >> 8] * 256 + (r & 255);
    const ulonglong2* pr = (const ulonglong2*)&g_logits[(size_t)rr * 64 + 36];
    ulonglong2 p0 = pr[0], p1 = pr[1], p2 = pr[2], p3 = pr[3];
    int wt = tgt - 1000;
    float m = -1e30f, se = 0.f;
    for (int w = warp; w < 19000; w += 4) {
        const ulonglong2* wr = (const ulonglong2*)(tw2 + (size_t)w * 16);
        ulonglong2 q0 = wr[0], q1 = wr[1], q2 = wr[2], q3 = wr[3];
        ull a = 0ull;
        ffma2(a, p0.x, q0.x); ffma2(a, p0.y, q0.y);
        ffma2(a, p1.x, q1.x); ffma2(a, p1.y, q1.y);
        ffma2(a, p2.x, q2.x); ffma2(a, p2.y, q2.y);
        ffma2(a, p3.x, q3.x); ffma2(a, p3.y, q3.y);
        float l = pairsum(a);
        if (w == wt) s_tl[lane] = l;
        if (l > m) { se = se * __expf(m - l) + 1.f; m = l; }
        else       se += __expf(l - m);
    }
    s_m[warp][lane] = m; s_s[warp][lane] = se;
    __syncthreads();
    if (warp == 0) {
        float M = s_m[0][lane];
        for (int q = 1; q < 4; q++) M = fmaxf(M, s_m[q][lane]);
        float S = 0.f;
        for (int q = 0; q < 4; q++) S += s_s[q][lane] * __expf(s_m[q][lane] - M);
        if (tgt >= 1000) g_ct[r] = (M + logf(S)) - s_tl[lane];
    }
}

// ---------- tail clusters 0/1 (rare rows), early exit ----------
__global__ void __launch_bounds__(128)
k_tail01(const float* __restrict__ tp0, const float* __restrict__ tw0,
         const float* __restrict__ tp1, const float* __restrict__ tw1,
         const int* __restrict__ target) {
    int r = blockIdx.x;
    int tgt = target[r];
    if (tgt < 30 || tgt >= 1000) return;
    int lo, nw, d; const float *P, *W;
    if (tgt < 100) { lo = 30; nw = 70; d = 256; P = tp0; W = tw0; }
    else           { lo = 100; nw = 900; d = 64; P = tp1; W = tw1; }
    int tid = threadIdx.x, lane = tid & 31, warp = tid >> 5;
    int rr = g_rev[r >> 8] * 256 + (r & 255);
    __shared__ float xs[HH], proj[256], rm[128], rs[128], s_tl;
    const float* xr = g_h2 + (size_t)rr * HH;
    for (int i = tid; i < HH; i += 128) xs[i] = xr[i];
    __syncthreads();
    for (int p = warp; p < d; p += 4) {
        const float* wr = P + (size_t)p * HH;
        float s = 0.f;
        for (int k = lane; k < HH; k += 32) s = fmaf(xs[k], wr[k], s);
#pragma unroll
        for (int off = 16; off; off >>= 1) s += __shfl_xor_sync(0xffffffffu, s, off);
        if (lane == 0) proj[p] = s;
    }
    __syncthreads();
    float m = -1e30f, se = 0.f;
    for (int w = tid; w < nw; w += 128) {
        const float* wr = W + (size_t)w * d;
        float l = 0.f;
        for (int k = 0; k < d; k++) l = fmaf(proj[k], wr[k], l);
        if (w == tgt - lo) s_tl = l;
        if (l > m) { se = se * __expf(m - l) + 1.f; m = l; }
        else       se += __expf(l - m);
    }
    rm[tid] = m; rs[tid] = se;
    __syncthreads();
    if (tid == 0) {
        float M = -1e30f;
        for (int i = 0; i < 128; i++) M = fmaxf(M, rm[i]);
        float S = 0.f;
        for (int i = 0; i < 128; i++) S += rs[i] * __expf(rm[i] - M);
        g_ct[r] = (M + logf(S)) - s_tl;
    }
}

// ---------- assemble + deterministic sum ----------
__global__ void k_final(const int* __restrict__ target) {
    int r = blockIdx.x * blockDim.x + threadIdx.x;
    if (r >= NROWS) return;
    int tgt = target[r];
    int rr = g_rev[r >> 8] * 256 + (r & 255);
    float nll;
    if (tgt == 0) nll = 0.f;
    else if (tgt < 30) nll = g_hl[r] - g_logits[(size_t)rr * 64 + tgt];
    else {
        int ci = tgt < 100 ? 0 : (tgt < 1000 ? 1 : 2);
        nll = (g_hl[r] - g_logits[(size_t)rr * 64 + 30 + ci]) + g_ct[r];
    }
    g_nll[r] = nll;
}

__global__ void k_sum(float* __restrict__ out) {
    __shared__ float sd[256];
    int tid = threadIdx.x;
    float s = 0.f;
    for (int i = tid; i < NROWS; i += 256) s += g_nll[i];
    sd[tid] = s;
    __syncthreads();
    for (int st = 128; st; st >>= 1) {
        if (tid < st) sd[tid] += sd[tid + st];
        __syncthreads();
    }
    if (tid == 0) out[0] = sd[0];
}

#define RNN_SMEM ((24 * HH + 2 * 32 * 257) * 4)

extern "C" void kernel_launch(void* const* d_in, const int* in_sizes, int n_in,
                              void* d_out, int out_size) {
    const float* z      = (const float*)d_in[0];
    const float* emb    = (const float*)d_in[1];
    const float* l2h_w  = (const float*)d_in[2];
    const float* l2h_b  = (const float*)d_in[3];
    const float* r0wih  = (const float*)d_in[4];
    const float* r0whh  = (const float*)d_in[5];
    const float* r0bih  = (const float*)d_in[6];
    const float* r0bhh  = (const float*)d_in[7];
    const float* r1wih  = (const float*)d_in[8];
    const float* r1whh  = (const float*)d_in[9];
    const float* r1bih  = (const float*)d_in[10];
    const float* r1bhh  = (const float*)d_in[11];
    const float* head_w = (const float*)d_in[12];
    const float* tp0    = (const float*)d_in[13];
    const float* tw0    = (const float*)d_in[14];
    const float* tp1    = (const float*)d_in[15];
    const float* tw1    = (const float*)d_in[16];
    const float* tp2    = (const float*)d_in[17];
    const float* tw2    = (const float*)d_in[18];
    const int*   inp    = (const int*)d_in[19];
    const int*   target = (const int*)d_in[20];
    const int*   length = (const int*)d_in[21];
    float* out = (float*)d_out;

    __nv_bfloat16* gh1b = nullptr; __nv_bfloat16* gh2b = nullptr;
    __nv_bfloat16* ghidb = nullptr;
    float* gh2 = nullptr; float* gz = nullptr; float* gpw = nullptr;
    float* gpre = nullptr; float* glog = nullptr;
    cudaGetSymbolAddress((void**)&gh1b, g_h1b);
    cudaGetSymbolAddress((void**)&gh2b, g_h2b);
    cudaGetSymbolAddress((void**)&gh2, g_h2);
    cudaGetSymbolAddress((void**)&gz, g_zero);
    cudaGetSymbolAddress((void**)&gpw, g_pw);
    cudaGetSymbolAddress((void**)&ghidb, g_hiddenb);
    cudaGetSymbolAddress((void**)&gpre, g_pre);
    cudaGetSymbolAddress((void**)&glog, g_logits);

    cudaFuncSetAttribute(k_rnn_fused, cudaFuncAttributeMaxDynamicSharedMemorySize, RNN_SMEM);

    k_preptok<<<1, 256>>>(length, inp);
    k_hidden<<<(2 * BB * HH) / 256, 256>>>(z, l2h_w, l2h_b);

    // layer 0 input pre-activations: emb[tok] @ W0ih^T + b0ih + b0hh
    k_sgemm<<<dim3(64, 16), 256>>>(emb, r0wih, r0bih, r0bhh, gpre, 512, HH, 1);
    // fused 2-layer recurrence (bf16 hidden-state storage)
    k_rnn_fused<<<NBLK, 256, RNN_SMEM>>>(r0whh, r1wih, r1whh, gpre,
                                         r1bih, r1bhh, ghidb, gh1b, gh2, gh2b);

    k_pack<<<64 * HH / 256, 256>>>(head_w, tp2);
    // packed head + tail2-proj logits: [8192 x 64]
    k_sgemm<<<dim3(64, 1), 256>>>(gh2, gpw, gz, gz, glog, HH, 64, 0);

    k_head<<<NROWS / 256, 256>>>();
    k_tail2<<<NROWS / 32, 128>>>(tw2, target);
    k_tail01<<<NROWS, 128>>>(tp0, tw0, tp1, tw1, target);
    k_final<<<NROWS / 256, 256>>>(target);
    k_sum<<<1, 256>>>(out);
    (void)in_sizes; (void)n_in; (void)out_size;
}